// round 3
// baseline (speedup 1.0000x reference)
#include <cuda_runtime.h>
#include <cuda_fp16.h>
#include <cstdint>
#include <math.h>

// ---------------------------------------------------------------------------
// QuantDeepseekMLP: out = qlin(silu(qlin(x,Wg,sg)) * qlin(x,Wu,su), Wd, sd)
// M=4096 tokens, H=5120, I=12288. Weights int8 semantics [out,in] row-major,
// per-output-row scale s; dequant = w * s / 127 applied post-accumulation.
// NOTE: harness may store the int8 arrays widened to int32 or float32 —
// we detect the storage dtype on-device and convert accordingly.
// Strategy: fp16 mma.sync GEMMs (small-int -> fp16 is exact), fp32 accum.
// ---------------------------------------------------------------------------

#define Mdim 4096
#define Hdim 5120
#define Idim 12288

// Scratch (static __device__ arrays: allocation-free rule)
__device__ __half g_x16[(size_t)Mdim * Hdim];     // x in fp16
__device__ __half g_wg16[(size_t)Idim * Hdim];    // w_gate fp16
__device__ __half g_wu16[(size_t)Idim * Hdim];    // w_up   fp16
__device__ __half g_wd16[(size_t)Hdim * Idim];    // w_down fp16
__device__ __half g_gate[(size_t)Mdim * Idim];    // gate pre-activation (scaled)
__device__ __half g_h[(size_t)Mdim * Idim];       // silu(gate)*up

// Weight storage dtype flag: 0 = int8, 1 = int32, 2 = float32
__device__ int g_wflag;

// ------------------------- dtype detection --------------------------------
__global__ void detect_w_kernel(const int* __restrict__ w) {
    if (threadIdx.x == 0 && blockIdx.x == 0) {
        int all_i32 = 1, all_f32 = 1;
        for (int i = 0; i < 256; i++) {
            int v = w[i];                    // safe: buffer >= 256 elements in
            if (v < -127 || v > 127) all_i32 = 0;   // any interpretation
            float f = __int_as_float(v);
            if (!(isfinite(f) && fabsf(f) <= 127.0f && f == rintf(f)))
                all_f32 = 0;
        }
        g_wflag = all_i32 ? 1 : (all_f32 ? 2 : 0);
    }
}

// ------------------------------ converters --------------------------------
__global__ void cvt_f32_f16_kernel(const float* __restrict__ in,
                                   __half* __restrict__ out, int n) {
    int i = (blockIdx.x * blockDim.x + threadIdx.x) * 4;
    if (i < n) {
        float4 v = *(const float4*)(in + i);
        *(__half2*)(out + i)     = __floats2half2_rn(v.x, v.y);
        *(__half2*)(out + i + 2) = __floats2half2_rn(v.z, v.w);
    }
}

// Weight converter: handles int8 / int32 / float32 storage, 8 elems/thread.
__global__ void cvt_w_f16_kernel(const void* __restrict__ in,
                                 __half* __restrict__ out, int n) {
    const int flag = g_wflag;
    int i = (blockIdx.x * blockDim.x + threadIdx.x) * 8;
    if (i >= n) return;
    float v[8];
    if (flag == 1) {             // int32 storage
        const int4* p = (const int4*)((const int*)in + i);
        int4 a = p[0], b = p[1];
        v[0] = (float)a.x; v[1] = (float)a.y; v[2] = (float)a.z; v[3] = (float)a.w;
        v[4] = (float)b.x; v[5] = (float)b.y; v[6] = (float)b.z; v[7] = (float)b.w;
    } else if (flag == 2) {      // float32 storage
        const float4* p = (const float4*)((const float*)in + i);
        float4 a = p[0], b = p[1];
        v[0] = a.x; v[1] = a.y; v[2] = a.z; v[3] = a.w;
        v[4] = b.x; v[5] = b.y; v[6] = b.z; v[7] = b.w;
    } else {                     // true int8 storage
        uint2 raw = *(const uint2*)((const int8_t*)in + i);
        const int8_t* b = (const int8_t*)&raw;
        #pragma unroll
        for (int j = 0; j < 8; j++) v[j] = (float)b[j];
    }
    #pragma unroll
    for (int j = 0; j < 8; j += 2)
        *(__half2*)(out + i + j) = __floats2half2_rn(v[j], v[j + 1]);
}

// ------------------------------- GEMM -------------------------------------
// C[m,n] = sum_k A[m,k]*B[n,k], both K-contiguous ("NT" layout).
// BM=128, BN=128, BK=32, 256 threads = 8 warps (2x4), warp tile 64x32,
// mma.sync.m16n8k16 fp16->fp32, cp.async double buffered.

#define BM 128
#define BN 128
#define BKg 32
#define PAD 8
#define GEMM_THREADS 256

__device__ __forceinline__ void cp_async16(void* smem, const void* gmem) {
    unsigned s = (unsigned)__cvta_generic_to_shared(smem);
    asm volatile("cp.async.cg.shared.global [%0], [%1], 16;\n"
                 :: "r"(s), "l"(gmem));
}
__device__ __forceinline__ void cp_commit() {
    asm volatile("cp.async.commit_group;\n" ::: "memory");
}
__device__ __forceinline__ void cp_wait_all() {
    asm volatile("cp.async.wait_group 0;\n" ::: "memory");
}

// MODE 0: store acc*scale as fp16 (gate buffer)
// MODE 1: up path: h = silu(gate_in) * (acc*scale), store fp16
// MODE 2: down path: store acc*scale as fp32 (final output)
template <int MODE>
__global__ __launch_bounds__(GEMM_THREADS)
void gemm_kernel(const __half* __restrict__ A, const __half* __restrict__ Bw,
                 const float* __restrict__ scale,
                 const __half* __restrict__ gate_in,
                 void* __restrict__ outp, int N, int K) {
    __shared__ __half As[2][BM][BKg + PAD];
    __shared__ __half Bs[2][BN][BKg + PAD];

    const int m0 = blockIdx.y * BM;
    const int n0 = blockIdx.x * BN;
    const int t = threadIdx.x;
    const int lane = t & 31;
    const int warp = t >> 5;
    const int wm = (warp >> 2) * 64;  // warp M offset within CTA
    const int wn = (warp & 3) * 32;   // warp N offset within CTA

    float acc[4][4][4];
    #pragma unroll
    for (int a = 0; a < 4; a++)
        #pragma unroll
        for (int b = 0; b < 4; b++)
            #pragma unroll
            for (int c = 0; c < 4; c++) acc[a][b][c] = 0.f;

    // tile loader: BM*BKg/8 = 512 16B-chunks per matrix, 2 per thread
    auto load_tile = [&](int stage, int k0) {
        #pragma unroll
        for (int c = 0; c < 2; c++) {
            int idx = t + c * GEMM_THREADS;       // 0..511
            int row = idx >> 2;                    // 4 chunks/row (BK=32)
            int col = (idx & 3) * 8;
            cp_async16(&As[stage][row][col],
                       A + (size_t)(m0 + row) * K + k0 + col);
            cp_async16(&Bs[stage][row][col],
                       Bw + (size_t)(n0 + row) * K + k0 + col);
        }
        cp_commit();
    };

    load_tile(0, 0);
    const int KT = K / BKg;

    for (int kt = 0; kt < KT; kt++) {
        cp_wait_all();
        __syncthreads();
        if (kt + 1 < KT) load_tile((kt + 1) & 1, (kt + 1) * BKg);
        const int st = kt & 1;

        #pragma unroll
        for (int ks = 0; ks < BKg; ks += 16) {
            uint32_t af[4][4], bf[4][2];
            #pragma unroll
            for (int mi = 0; mi < 4; mi++) {
                int r = wm + mi * 16 + (lane >> 2);
                int c = ks + (lane & 3) * 2;
                af[mi][0] = *(const uint32_t*)&As[st][r][c];
                af[mi][1] = *(const uint32_t*)&As[st][r + 8][c];
                af[mi][2] = *(const uint32_t*)&As[st][r][c + 8];
                af[mi][3] = *(const uint32_t*)&As[st][r + 8][c + 8];
            }
            #pragma unroll
            for (int ni = 0; ni < 4; ni++) {
                int r = wn + ni * 8 + (lane >> 2);
                int c = ks + (lane & 3) * 2;
                bf[ni][0] = *(const uint32_t*)&Bs[st][r][c];
                bf[ni][1] = *(const uint32_t*)&Bs[st][r][c + 8];
            }
            #pragma unroll
            for (int mi = 0; mi < 4; mi++)
                #pragma unroll
                for (int ni = 0; ni < 4; ni++) {
                    asm volatile(
                        "mma.sync.aligned.m16n8k16.row.col.f32.f16.f16.f32 "
                        "{%0,%1,%2,%3}, {%4,%5,%6,%7}, {%8,%9}, {%0,%1,%2,%3};\n"
                        : "+f"(acc[mi][ni][0]), "+f"(acc[mi][ni][1]),
                          "+f"(acc[mi][ni][2]), "+f"(acc[mi][ni][3])
                        : "r"(af[mi][0]), "r"(af[mi][1]),
                          "r"(af[mi][2]), "r"(af[mi][3]),
                          "r"(bf[ni][0]), "r"(bf[ni][1]));
                }
        }
    }

    // ------------------------------- epilogue -----------------------------
    const float inv127 = 1.0f / 127.0f;
    #pragma unroll
    for (int mi = 0; mi < 4; mi++) {
        int r = m0 + wm + mi * 16 + (lane >> 2);
        #pragma unroll
        for (int ni = 0; ni < 4; ni++) {
            int col = n0 + wn + ni * 8 + (lane & 3) * 2;
            float s0 = scale[col] * inv127;
            float s1 = scale[col + 1] * inv127;
            float v00 = acc[mi][ni][0] * s0, v01 = acc[mi][ni][1] * s1;
            float v10 = acc[mi][ni][2] * s0, v11 = acc[mi][ni][3] * s1;
            size_t off0 = (size_t)r * N + col;
            size_t off1 = (size_t)(r + 8) * N + col;
            if (MODE == 0) {
                __half* o = (__half*)outp;
                *(__half2*)(o + off0) = __floats2half2_rn(v00, v01);
                *(__half2*)(o + off1) = __floats2half2_rn(v10, v11);
            } else if (MODE == 1) {
                __half2 gA = *(const __half2*)(gate_in + off0);
                __half2 gB = *(const __half2*)(gate_in + off1);
                float g00 = __low2float(gA), g01 = __high2float(gA);
                float g10 = __low2float(gB), g11 = __high2float(gB);
                v00 *= g00 / (1.0f + __expf(-g00));
                v01 *= g01 / (1.0f + __expf(-g01));
                v10 *= g10 / (1.0f + __expf(-g10));
                v11 *= g11 / (1.0f + __expf(-g11));
                __half* o = (__half*)outp;
                *(__half2*)(o + off0) = __floats2half2_rn(v00, v01);
                *(__half2*)(o + off1) = __floats2half2_rn(v10, v11);
            } else {
                float* o = (float*)outp;
                *(float2*)(o + off0) = make_float2(v00, v01);
                *(float2*)(o + off1) = make_float2(v10, v11);
            }
        }
    }
}

// ------------------------------ launcher -----------------------------------
extern "C" void kernel_launch(void* const* d_in, const int* in_sizes, int n_in,
                              void* d_out, int out_size) {
    const float* x  = (const float*)d_in[0];
    const void*  wg = d_in[1];
    const float* sg = (const float*)d_in[2];
    const void*  wu = d_in[3];
    const float* su = (const float*)d_in[4];
    const void*  wd = d_in[5];
    const float* sd = (const float*)d_in[6];

    const int H = in_sizes[6];            // 5120 (s_down length)
    const int I = in_sizes[2];            // 12288 (s_gate length)
    const int M = in_sizes[0] / H;        // 4096

    __half *px16, *pwg, *pwu, *pwd, *pgate, *ph;
    cudaGetSymbolAddress((void**)&px16, g_x16);
    cudaGetSymbolAddress((void**)&pwg,  g_wg16);
    cudaGetSymbolAddress((void**)&pwu,  g_wu16);
    cudaGetSymbolAddress((void**)&pwd,  g_wd16);
    cudaGetSymbolAddress((void**)&pgate, g_gate);
    cudaGetSymbolAddress((void**)&ph,   g_h);

    // Detect weight storage dtype (int8 vs int32 vs float32)
    detect_w_kernel<<<1, 32>>>((const int*)wg);

    // Prologue: convert inputs to fp16
    {
        int n = M * H;
        cvt_f32_f16_kernel<<<(n / 4 + 255) / 256, 256>>>(x, px16, n);
        int nw = I * H;
        int g8 = (nw / 8 + 255) / 256;
        cvt_w_f16_kernel<<<g8, 256>>>(wg, pwg, nw);
        cvt_w_f16_kernel<<<g8, 256>>>(wu, pwu, nw);
        cvt_w_f16_kernel<<<g8, 256>>>(wd, pwd, nw);
    }

    // GEMM 1: gate = (x @ Wg^T) * sg/127         [M, I] fp16
    {
        dim3 grid(I / BN, M / BM);
        gemm_kernel<0><<<grid, GEMM_THREADS>>>(px16, pwg, sg, nullptr,
                                               (void*)pgate, I, H);
    }
    // GEMM 2: h = silu(gate) * ((x @ Wu^T) * su/127)   [M, I] fp16
    {
        dim3 grid(I / BN, M / BM);
        gemm_kernel<1><<<grid, GEMM_THREADS>>>(px16, pwu, su, pgate,
                                               (void*)ph, I, H);
    }
    // GEMM 3: out = (h @ Wd^T) * sd/127          [M, H] fp32
    {
        dim3 grid(H / BN, M / BM);
        gemm_kernel<2><<<grid, GEMM_THREADS>>>(ph, pwd, sd, nullptr,
                                               d_out, H, I);
    }
}

// round 5
// speedup vs baseline: 1.4350x; 1.4350x over previous
#include <cuda_runtime.h>
#include <cuda_fp16.h>
#include <cstdint>
#include <math.h>

// ---------------------------------------------------------------------------
// QuantDeepseekMLP on sm_103a (legacy mma.sync path — tcgen05 PTX is not
// accepted by this harness's compute_103 virtual arch).
// out = qlin(silu(qlin(x,Wg,sg)) * qlin(x,Wu,su), Wd, sd)
// GEMM: C[m,n] = sum_k A[m,k]*B[n,k] (both K-contiguous).
// CTA tile 128x256x64, 8 warps (2x4), warp tile 64x64, ldmatrix + mma.sync
// m16n8k16 fp16->fp32, SW128-swizzled smem, 3-stage cp.async pipeline.
// ---------------------------------------------------------------------------

#define Mdim 4096
#define Hdim 5120
#define Idim 12288

__device__ __half g_x16[(size_t)Mdim * Hdim];
__device__ __half g_wg16[(size_t)Idim * Hdim];
__device__ __half g_wu16[(size_t)Idim * Hdim];
__device__ __half g_wd16[(size_t)Hdim * Idim];
__device__ __half g_gate[(size_t)Mdim * Idim];
__device__ __half g_h[(size_t)Mdim * Idim];
__device__ int g_wflag;   // 0=int8, 1=int32, 2=float32 weight storage

// ------------------------- dtype detection --------------------------------
__global__ void detect_w_kernel(const int* __restrict__ w) {
    if (threadIdx.x == 0 && blockIdx.x == 0) {
        int all_i32 = 1, all_f32 = 1;
        for (int i = 0; i < 256; i++) {
            int v = w[i];
            if (v < -127 || v > 127) all_i32 = 0;
            float f = __int_as_float(v);
            if (!(isfinite(f) && fabsf(f) <= 127.0f && f == rintf(f)))
                all_f32 = 0;
        }
        g_wflag = all_i32 ? 1 : (all_f32 ? 2 : 0);
    }
}

// ------------------------------ converters --------------------------------
__global__ void cvt_f32_f16_kernel(const float* __restrict__ in,
                                   __half* __restrict__ out, int n) {
    int i = (blockIdx.x * blockDim.x + threadIdx.x) * 4;
    if (i < n) {
        float4 v = *(const float4*)(in + i);
        *(__half2*)(out + i)     = __floats2half2_rn(v.x, v.y);
        *(__half2*)(out + i + 2) = __floats2half2_rn(v.z, v.w);
    }
}

__global__ void cvt_w_f16_kernel(const void* __restrict__ in,
                                 __half* __restrict__ out, int n) {
    const int flag = g_wflag;
    int i = (blockIdx.x * blockDim.x + threadIdx.x) * 8;
    if (i >= n) return;
    float v[8];
    if (flag == 1) {
        const int4* p = (const int4*)((const int*)in + i);
        int4 a = p[0], b = p[1];
        v[0]=(float)a.x; v[1]=(float)a.y; v[2]=(float)a.z; v[3]=(float)a.w;
        v[4]=(float)b.x; v[5]=(float)b.y; v[6]=(float)b.z; v[7]=(float)b.w;
    } else if (flag == 2) {
        const float4* p = (const float4*)((const float*)in + i);
        float4 a = p[0], b = p[1];
        v[0]=a.x; v[1]=a.y; v[2]=a.z; v[3]=a.w;
        v[4]=b.x; v[5]=b.y; v[6]=b.z; v[7]=b.w;
    } else {
        uint2 raw = *(const uint2*)((const int8_t*)in + i);
        const int8_t* b = (const int8_t*)&raw;
        #pragma unroll
        for (int j = 0; j < 8; j++) v[j] = (float)b[j];
    }
    #pragma unroll
    for (int j = 0; j < 8; j += 2)
        *(__half2*)(out + i + j) = __floats2half2_rn(v[j], v[j + 1]);
}

// --------------------------- PTX helpers -----------------------------------
__device__ __forceinline__ uint32_t smem_u32(const void* p) {
    return (uint32_t)__cvta_generic_to_shared(p);
}
__device__ __forceinline__ void cp_async16(uint32_t smem, const void* gmem) {
    asm volatile("cp.async.cg.shared.global [%0], [%1], 16;\n" :: "r"(smem), "l"(gmem));
}
__device__ __forceinline__ void cp_commit() {
    asm volatile("cp.async.commit_group;\n" ::: "memory");
}
template <int N>
__device__ __forceinline__ void cp_wait() {
    asm volatile("cp.async.wait_group %0;\n" :: "n"(N) : "memory");
}
__device__ __forceinline__ void ldsm_x4(uint32_t* r, uint32_t addr) {
    asm volatile("ldmatrix.sync.aligned.m8n8.x4.shared.b16 {%0,%1,%2,%3}, [%4];"
                 : "=r"(r[0]), "=r"(r[1]), "=r"(r[2]), "=r"(r[3]) : "r"(addr));
}
__device__ __forceinline__ void mma16816(float* d, const uint32_t* a,
                                         const uint32_t* b) {
    asm volatile(
        "mma.sync.aligned.m16n8k16.row.col.f32.f16.f16.f32 "
        "{%0,%1,%2,%3}, {%4,%5,%6,%7}, {%8,%9}, {%0,%1,%2,%3};\n"
        : "+f"(d[0]), "+f"(d[1]), "+f"(d[2]), "+f"(d[3])
        : "r"(a[0]), "r"(a[1]), "r"(a[2]), "r"(a[3]), "r"(b[0]), "r"(b[1]));
}

#define SWZ(o) ((o) ^ (((o) >> 3) & 0x70))

// ------------------------------- GEMM --------------------------------------
// Stage layout: A rows 0..127 (128B pitch, SW128) then B rows 0..255.
#define STAGES 3
#define A_BYTES (128 * 128)
#define STAGE_BYTES (A_BYTES + 256 * 128)   // 48 KB
#define SMEM_SZ (STAGES * STAGE_BYTES + 1024)

template <int MODE>   // 0: fp16 out (gate); 1: silu(gate)*v fp16; 2: fp32 out
__global__ __launch_bounds__(256, 1)
void gemm_kernel(const __half* __restrict__ A, const __half* __restrict__ Bw,
                 const float* __restrict__ scale,
                 const __half* __restrict__ gate_in,
                 void* __restrict__ outp, int N, int K) {
    extern __shared__ char smem_raw[];
    const uint32_t sbase = (smem_u32(smem_raw) + 1023) & ~1023u;

    const int tid  = threadIdx.x;
    const int lane = tid & 31;
    const int warp = tid >> 5;
    const int wm = (warp >> 2) * 64;          // 0 or 64
    const int wn = (warp & 3) * 64;           // 0,64,128,192
    const int m0 = blockIdx.y * 128;
    const int n0 = blockIdx.x * 256;
    const int KT = K >> 6;

    const int g  = lane >> 3;                 // ldmatrix group 0..3
    const int li = lane & 7;

    const size_t pitch = (size_t)K * 2;
    const char* Ag = (const char*)A + (size_t)m0 * pitch;
    const char* Bg = (const char*)Bw + (size_t)n0 * pitch;

    float acc[4][8][4];
    #pragma unroll
    for (int a = 0; a < 4; a++)
        #pragma unroll
        for (int b = 0; b < 8; b++)
            #pragma unroll
            for (int c = 0; c < 4; c++) acc[a][b][c] = 0.f;

    auto load_stage = [&](int slot, int kt) {
        const size_t k0b = (size_t)kt * 128;
        const uint32_t ab = sbase + slot * STAGE_BYTES;
        const uint32_t bb = ab + A_BYTES;
        #pragma unroll
        for (int i = 0; i < 12; i++) {
            int idx = i * 256 + tid;          // 0..3071
            if (idx < 1024) {
                int r = idx >> 3, cb = (idx & 7) * 16;
                cp_async16(ab + SWZ(r * 128 + cb), Ag + (size_t)r * pitch + k0b + cb);
            } else {
                int j = idx - 1024;           // 0..2047
                int r = j >> 3, cb = (j & 7) * 16;
                cp_async16(bb + SWZ(r * 128 + cb), Bg + (size_t)r * pitch + k0b + cb);
            }
        }
        cp_commit();
    };

    load_stage(0, 0);
    if (KT > 1) load_stage(1, 1);

    // per-lane fragment row offsets (bytes within tile)
    uint32_t arow[4], brow[4];
    #pragma unroll
    for (int mi = 0; mi < 4; mi++)
        arow[mi] = (uint32_t)(wm + mi * 16 + ((g & 1) ? 8 : 0) + li) * 128;
    #pragma unroll
    for (int bi = 0; bi < 4; bi++)
        brow[bi] = (uint32_t)(wn + bi * 16 + ((g >> 1) ? 8 : 0) + li) * 128;
    const uint32_t acol = (g >> 1) ? 16u : 0u;
    const uint32_t bcol = (g & 1) ? 16u : 0u;

    for (int kt = 0; kt < KT; kt++) {
        if (kt + 1 < KT) cp_wait<1>(); else cp_wait<0>();
        __syncthreads();
        if (kt + 2 < KT) load_stage((kt + 2) % STAGES, kt + 2);

        const uint32_t ab = sbase + (kt % STAGES) * STAGE_BYTES;
        const uint32_t bb = ab + A_BYTES;

        #pragma unroll
        for (int ks = 0; ks < 4; ks++) {
            const uint32_t kb = ks * 32;
            uint32_t af[4][4], bf[4][4];
            #pragma unroll
            for (int mi = 0; mi < 4; mi++)
                ldsm_x4(af[mi], ab + SWZ(arow[mi] + kb + acol));
            #pragma unroll
            for (int bi = 0; bi < 4; bi++)
                ldsm_x4(bf[bi], bb + SWZ(brow[bi] + kb + bcol));
            #pragma unroll
            for (int mi = 0; mi < 4; mi++)
                #pragma unroll
                for (int nj = 0; nj < 8; nj++)
                    mma16816(acc[mi][nj], af[mi], &bf[nj >> 1][(nj & 1) * 2]);
        }
    }

    // ------------------------------ epilogue -------------------------------
    const float inv = 1.0f / 127.0f;
    #pragma unroll
    for (int mi = 0; mi < 4; mi++) {
        int r = m0 + wm + mi * 16 + (lane >> 2);
        #pragma unroll
        for (int nj = 0; nj < 8; nj++) {
            int col = n0 + wn + nj * 8 + (lane & 3) * 2;
            float s0 = scale[col] * inv;
            float s1 = scale[col + 1] * inv;
            float v00 = acc[mi][nj][0] * s0, v01 = acc[mi][nj][1] * s1;
            float v10 = acc[mi][nj][2] * s0, v11 = acc[mi][nj][3] * s1;
            size_t off0 = (size_t)r * N + col;
            size_t off1 = (size_t)(r + 8) * N + col;
            if (MODE == 2) {
                float* o = (float*)outp;
                *(float2*)(o + off0) = make_float2(v00, v01);
                *(float2*)(o + off1) = make_float2(v10, v11);
            } else {
                if (MODE == 1) {
                    __half2 gA = *(const __half2*)(gate_in + off0);
                    __half2 gB = *(const __half2*)(gate_in + off1);
                    float g00 = __low2float(gA), g01 = __high2float(gA);
                    float g10 = __low2float(gB), g11 = __high2float(gB);
                    v00 *= g00 / (1.0f + __expf(-g00));
                    v01 *= g01 / (1.0f + __expf(-g01));
                    v10 *= g10 / (1.0f + __expf(-g10));
                    v11 *= g11 / (1.0f + __expf(-g11));
                }
                __half* o = (__half*)outp;
                *(__half2*)(o + off0) = __floats2half2_rn(v00, v01);
                *(__half2*)(o + off1) = __floats2half2_rn(v10, v11);
            }
        }
    }
}

// ------------------------------ launcher -----------------------------------
extern "C" void kernel_launch(void* const* d_in, const int* in_sizes, int n_in,
                              void* d_out, int out_size) {
    const float* x  = (const float*)d_in[0];
    const void*  wg = d_in[1];
    const float* sg = (const float*)d_in[2];
    const void*  wu = d_in[3];
    const float* su = (const float*)d_in[4];
    const void*  wd = d_in[5];
    const float* sd = (const float*)d_in[6];

    const int H = in_sizes[6];            // 5120
    const int I = in_sizes[2];            // 12288
    const int M = in_sizes[0] / H;        // 4096

    __half *px16, *pwg, *pwu, *pwd, *pgate, *ph;
    cudaGetSymbolAddress((void**)&px16, g_x16);
    cudaGetSymbolAddress((void**)&pwg,  g_wg16);
    cudaGetSymbolAddress((void**)&pwu,  g_wu16);
    cudaGetSymbolAddress((void**)&pwd,  g_wd16);
    cudaGetSymbolAddress((void**)&pgate, g_gate);
    cudaGetSymbolAddress((void**)&ph,   g_h);

    cudaFuncSetAttribute(gemm_kernel<0>, cudaFuncAttributeMaxDynamicSharedMemorySize, SMEM_SZ);
    cudaFuncSetAttribute(gemm_kernel<1>, cudaFuncAttributeMaxDynamicSharedMemorySize, SMEM_SZ);
    cudaFuncSetAttribute(gemm_kernel<2>, cudaFuncAttributeMaxDynamicSharedMemorySize, SMEM_SZ);

    detect_w_kernel<<<1, 32>>>((const int*)wg);

    {
        int n = M * H;
        cvt_f32_f16_kernel<<<(n / 4 + 255) / 256, 256>>>(x, px16, n);
        int nw = I * H;
        int g8 = (nw / 8 + 255) / 256;
        cvt_w_f16_kernel<<<g8, 256>>>(wg, pwg, nw);
        cvt_w_f16_kernel<<<g8, 256>>>(wu, pwu, nw);
        cvt_w_f16_kernel<<<g8, 256>>>(wd, pwd, nw);
    }

    dim3 g1(I / 256, M / 128);  // (48, 32)
    gemm_kernel<0><<<g1, 256, SMEM_SZ>>>(px16, pwg, sg, nullptr, (void*)pgate, I, H);
    gemm_kernel<1><<<g1, 256, SMEM_SZ>>>(px16, pwu, su, pgate, (void*)ph, I, H);
    dim3 g3(H / 256, M / 128);  // (20, 32)
    gemm_kernel<2><<<g3, 256, SMEM_SZ>>>(ph, pwd, sd, nullptr, d_out, H, I);
}

// round 6
// speedup vs baseline: 1.5098x; 1.0521x over previous
#include <cuda_runtime.h>
#include <cuda_fp16.h>
#include <cstdint>
#include <math.h>

// ---------------------------------------------------------------------------
// QuantDeepseekMLP on sm_103a (legacy mma.sync path; tcgen05 PTX rejected by
// the harness's compute_103 virtual arch).
// out = qlin(silu(qlin(x,Wg,sg)) * qlin(x,Wu,su), Wd, sd)
// R6: m-tile-fastest grid (L2 locality), fused gate+up GEMM (interleaved B),
// single fused weight-convert kernel (also shifts GEMMs into ncu's window).
// ---------------------------------------------------------------------------

#define Mdim 4096
#define Hdim 5120
#define Idim 12288

__device__ __half g_x16[(size_t)Mdim * Hdim];
__device__ __half g_wg16[(size_t)Idim * Hdim];
__device__ __half g_wu16[(size_t)Idim * Hdim];
__device__ __half g_wd16[(size_t)Hdim * Idim];
__device__ __half g_h[(size_t)Mdim * Idim];
__device__ int g_wflag;   // 0=int8, 1=int32, 2=float32 weight storage

// ------------------------- dtype detection --------------------------------
__global__ void detect_w_kernel(const int* __restrict__ w) {
    if (threadIdx.x == 0 && blockIdx.x == 0) {
        int all_i32 = 1, all_f32 = 1;
        for (int i = 0; i < 256; i++) {
            int v = w[i];
            if (v < -127 || v > 127) all_i32 = 0;
            float f = __int_as_float(v);
            if (!(isfinite(f) && fabsf(f) <= 127.0f && f == rintf(f)))
                all_f32 = 0;
        }
        g_wflag = all_i32 ? 1 : (all_f32 ? 2 : 0);
    }
}

// ------------------------------ converters --------------------------------
__global__ void cvt_f32_f16_kernel(const float* __restrict__ in,
                                   __half* __restrict__ out, int n) {
    int i = (blockIdx.x * blockDim.x + threadIdx.x) * 4;
    if (i < n) {
        float4 v = *(const float4*)(in + i);
        *(__half2*)(out + i)     = __floats2half2_rn(v.x, v.y);
        *(__half2*)(out + i + 2) = __floats2half2_rn(v.z, v.w);
    }
}

__device__ __forceinline__ void cvt_w8(const void* in, __half* out, int i) {
    const int flag = g_wflag;
    float v[8];
    if (flag == 1) {
        const int4* p = (const int4*)((const int*)in + i);
        int4 a = p[0], b = p[1];
        v[0]=(float)a.x; v[1]=(float)a.y; v[2]=(float)a.z; v[3]=(float)a.w;
        v[4]=(float)b.x; v[5]=(float)b.y; v[6]=(float)b.z; v[7]=(float)b.w;
    } else if (flag == 2) {
        const float4* p = (const float4*)((const float*)in + i);
        float4 a = p[0], b = p[1];
        v[0]=a.x; v[1]=a.y; v[2]=a.z; v[3]=a.w;
        v[4]=b.x; v[5]=b.y; v[6]=b.z; v[7]=b.w;
    } else {
        uint2 raw = *(const uint2*)((const int8_t*)in + i);
        const int8_t* b = (const int8_t*)&raw;
        #pragma unroll
        for (int j = 0; j < 8; j++) v[j] = (float)b[j];
    }
    #pragma unroll
    for (int j = 0; j < 8; j += 2)
        *(__half2*)(out + i + j) = __floats2half2_rn(v[j], v[j + 1]);
}

// One launch converts all three weight matrices (blockIdx.y selects).
__global__ void cvt_w_all_kernel(const void* w0, const void* w1, const void* w2,
                                 __half* o0, __half* o1, __half* o2, int n) {
    int i = (blockIdx.x * blockDim.x + threadIdx.x) * 8;
    if (i >= n) return;
    const void* src = (blockIdx.y == 0) ? w0 : (blockIdx.y == 1) ? w1 : w2;
    __half* dst = (blockIdx.y == 0) ? o0 : (blockIdx.y == 1) ? o1 : o2;
    cvt_w8(src, dst, i);
}

// --------------------------- PTX helpers -----------------------------------
__device__ __forceinline__ uint32_t smem_u32(const void* p) {
    return (uint32_t)__cvta_generic_to_shared(p);
}
__device__ __forceinline__ void cp_async16(uint32_t smem, const void* gmem) {
    asm volatile("cp.async.cg.shared.global [%0], [%1], 16;\n" :: "r"(smem), "l"(gmem));
}
__device__ __forceinline__ void cp_commit() {
    asm volatile("cp.async.commit_group;\n" ::: "memory");
}
template <int N>
__device__ __forceinline__ void cp_wait() {
    asm volatile("cp.async.wait_group %0;\n" :: "n"(N) : "memory");
}
__device__ __forceinline__ void ldsm_x4(uint32_t* r, uint32_t addr) {
    asm volatile("ldmatrix.sync.aligned.m8n8.x4.shared.b16 {%0,%1,%2,%3}, [%4];"
                 : "=r"(r[0]), "=r"(r[1]), "=r"(r[2]), "=r"(r[3]) : "r"(addr));
}
__device__ __forceinline__ void mma16816(float* d, const uint32_t* a,
                                         const uint32_t* b) {
    asm volatile(
        "mma.sync.aligned.m16n8k16.row.col.f32.f16.f16.f32 "
        "{%0,%1,%2,%3}, {%4,%5,%6,%7}, {%8,%9}, {%0,%1,%2,%3};\n"
        : "+f"(d[0]), "+f"(d[1]), "+f"(d[2]), "+f"(d[3])
        : "r"(a[0]), "r"(a[1]), "r"(a[2]), "r"(a[3]), "r"(b[0]), "r"(b[1]));
}

#define SWZ(o) ((o) ^ (((o) >> 3) & 0x70))

#define STAGES 3
#define A_BYTES (128 * 128)
#define STAGE_BYTES (A_BYTES + 256 * 128)   // 48 KB
#define SMEM_SZ (STAGES * STAGE_BYTES + 1024)

// ----------------------- shared GEMM mainloop body -------------------------
// (templated via a load functor would bloat; we write two kernels sharing the
//  fragment/mma structure)

// ===================== fused gate+up GEMM ===================================
// CTA output: h tile 128 rows x 128 cols. B smem (256 rows) interleaves
// 32-row blocks: [g(c0..31) | u(c0..31) | g(c32..63) | u(c32..63) | ...].
// Warp w (wn = w*64) owns virtual B rows wn..wn+63 = gate+up of cols
// [w*32, w*32+32). acc[..][nj] = gate, acc[..][nj+4] = up (same columns).
__global__ __launch_bounds__(256, 1)
void gemm_gateup(const __half* __restrict__ A, const __half* __restrict__ Bg_w,
                 const __half* __restrict__ Bu_w,
                 const float* __restrict__ sg, const float* __restrict__ su,
                 __half* __restrict__ outp, int N, int K) {
    extern __shared__ char smem_raw[];
    const uint32_t sbase = (smem_u32(smem_raw) + 1023) & ~1023u;

    const int tid  = threadIdx.x;
    const int lane = tid & 31;
    const int warp = tid >> 5;
    const int wm = (warp >> 2) * 64;
    const int wn = (warp & 3) * 64;           // virtual B-row offset
    const int m0 = blockIdx.x * 128;          // m fastest (L2 locality)
    const int n0 = blockIdx.y * 128;          // h column tile
    const int KT = K >> 6;

    const int g  = lane >> 3;
    const int li = lane & 7;

    const size_t pitch = (size_t)K * 2;
    const char* Ag = (const char*)A + (size_t)m0 * pitch;
    const char* Gg = (const char*)Bg_w + (size_t)n0 * pitch;
    const char* Ug = (const char*)Bu_w + (size_t)n0 * pitch;

    float acc[4][8][4];
    #pragma unroll
    for (int a = 0; a < 4; a++)
        #pragma unroll
        for (int b = 0; b < 8; b++)
            #pragma unroll
            for (int c = 0; c < 4; c++) acc[a][b][c] = 0.f;

    auto load_stage = [&](int slot, int kt) {
        const size_t k0b = (size_t)kt * 128;
        const uint32_t ab = sbase + slot * STAGE_BYTES;
        const uint32_t bb = ab + A_BYTES;
        #pragma unroll
        for (int i = 0; i < 12; i++) {
            int idx = i * 256 + tid;
            if (idx < 1024) {
                int r = idx >> 3, cb = (idx & 7) * 16;
                cp_async16(ab + SWZ(r * 128 + cb), Ag + (size_t)r * pitch + k0b + cb);
            } else {
                int j = idx - 1024;            // 0..2047
                int r = j >> 3, cb = (j & 7) * 16;
                int blk = r >> 5, within = r & 31;
                int w32 = (blk >> 1) * 32 + within;   // source row in 128-tile
                const char* src = (blk & 1) ? Ug : Gg;
                cp_async16(bb + SWZ(r * 128 + cb), src + (size_t)w32 * pitch + k0b + cb);
            }
        }
        cp_commit();
    };

    load_stage(0, 0);
    if (KT > 1) load_stage(1, 1);

    uint32_t arow[4], brow[4];
    #pragma unroll
    for (int mi = 0; mi < 4; mi++)
        arow[mi] = (uint32_t)(wm + mi * 16 + ((g & 1) ? 8 : 0) + li) * 128;
    #pragma unroll
    for (int bi = 0; bi < 4; bi++)
        brow[bi] = (uint32_t)(wn + bi * 16 + ((g >> 1) ? 8 : 0) + li) * 128;
    const uint32_t acol = (g >> 1) ? 16u : 0u;
    const uint32_t bcol = (g & 1) ? 16u : 0u;

    for (int kt = 0; kt < KT; kt++) {
        if (kt + 1 < KT) cp_wait<1>(); else cp_wait<0>();
        __syncthreads();
        if (kt + 2 < KT) load_stage((kt + 2) % STAGES, kt + 2);

        const uint32_t ab = sbase + (kt % STAGES) * STAGE_BYTES;
        const uint32_t bb = ab + A_BYTES;

        #pragma unroll
        for (int ks = 0; ks < 4; ks++) {
            const uint32_t kb = ks * 32;
            uint32_t af[4][4], bf[4][4];
            #pragma unroll
            for (int mi = 0; mi < 4; mi++)
                ldsm_x4(af[mi], ab + SWZ(arow[mi] + kb + acol));
            #pragma unroll
            for (int bi = 0; bi < 4; bi++)
                ldsm_x4(bf[bi], bb + SWZ(brow[bi] + kb + bcol));
            #pragma unroll
            for (int mi = 0; mi < 4; mi++)
                #pragma unroll
                for (int nj = 0; nj < 8; nj++)
                    mma16816(acc[mi][nj], af[mi], &bf[nj >> 1][(nj & 1) * 2]);
        }
    }

    // epilogue: h = silu(gate*sg/127) * (up*su/127), fp16
    const float inv = 1.0f / 127.0f;
    const int cbase = n0 + (wn >> 1);          // warp's 32-col block
    #pragma unroll
    for (int mi = 0; mi < 4; mi++) {
        int r = m0 + wm + mi * 16 + (lane >> 2);
        #pragma unroll
        for (int nj = 0; nj < 4; nj++) {
            int col = cbase + nj * 8 + (lane & 3) * 2;
            float sg0 = sg[col] * inv, sg1 = sg[col + 1] * inv;
            float su0 = su[col] * inv, su1 = su[col + 1] * inv;
            float g00 = acc[mi][nj][0] * sg0, g01 = acc[mi][nj][1] * sg1;
            float g10 = acc[mi][nj][2] * sg0, g11 = acc[mi][nj][3] * sg1;
            float u00 = acc[mi][nj + 4][0] * su0, u01 = acc[mi][nj + 4][1] * su1;
            float u10 = acc[mi][nj + 4][2] * su0, u11 = acc[mi][nj + 4][3] * su1;
            float h00 = u00 * g00 / (1.0f + __expf(-g00));
            float h01 = u01 * g01 / (1.0f + __expf(-g01));
            float h10 = u10 * g10 / (1.0f + __expf(-g10));
            float h11 = u11 * g11 / (1.0f + __expf(-g11));
            *(__half2*)(outp + (size_t)r * N + col)       = __floats2half2_rn(h00, h01);
            *(__half2*)(outp + (size_t)(r + 8) * N + col) = __floats2half2_rn(h10, h11);
        }
    }
}

// ===================== plain GEMM (down projection) =========================
__global__ __launch_bounds__(256, 1)
void gemm_down(const __half* __restrict__ A, const __half* __restrict__ Bw,
               const float* __restrict__ scale,
               float* __restrict__ outp, int N, int K) {
    extern __shared__ char smem_raw[];
    const uint32_t sbase = (smem_u32(smem_raw) + 1023) & ~1023u;

    const int tid  = threadIdx.x;
    const int lane = tid & 31;
    const int warp = tid >> 5;
    const int wm = (warp >> 2) * 64;
    const int wn = (warp & 3) * 64;
    const int m0 = blockIdx.x * 128;          // m fastest
    const int n0 = blockIdx.y * 256;
    const int KT = K >> 6;

    const int g  = lane >> 3;
    const int li = lane & 7;

    const size_t pitch = (size_t)K * 2;
    const char* Ag = (const char*)A + (size_t)m0 * pitch;
    const char* Bg = (const char*)Bw + (size_t)n0 * pitch;

    float acc[4][8][4];
    #pragma unroll
    for (int a = 0; a < 4; a++)
        #pragma unroll
        for (int b = 0; b < 8; b++)
            #pragma unroll
            for (int c = 0; c < 4; c++) acc[a][b][c] = 0.f;

    auto load_stage = [&](int slot, int kt) {
        const size_t k0b = (size_t)kt * 128;
        const uint32_t ab = sbase + slot * STAGE_BYTES;
        const uint32_t bb = ab + A_BYTES;
        #pragma unroll
        for (int i = 0; i < 12; i++) {
            int idx = i * 256 + tid;
            if (idx < 1024) {
                int r = idx >> 3, cb = (idx & 7) * 16;
                cp_async16(ab + SWZ(r * 128 + cb), Ag + (size_t)r * pitch + k0b + cb);
            } else {
                int j = idx - 1024;
                int r = j >> 3, cb = (j & 7) * 16;
                cp_async16(bb + SWZ(r * 128 + cb), Bg + (size_t)r * pitch + k0b + cb);
            }
        }
        cp_commit();
    };

    load_stage(0, 0);
    if (KT > 1) load_stage(1, 1);

    uint32_t arow[4], brow[4];
    #pragma unroll
    for (int mi = 0; mi < 4; mi++)
        arow[mi] = (uint32_t)(wm + mi * 16 + ((g & 1) ? 8 : 0) + li) * 128;
    #pragma unroll
    for (int bi = 0; bi < 4; bi++)
        brow[bi] = (uint32_t)(wn + bi * 16 + ((g >> 1) ? 8 : 0) + li) * 128;
    const uint32_t acol = (g >> 1) ? 16u : 0u;
    const uint32_t bcol = (g & 1) ? 16u : 0u;

    for (int kt = 0; kt < KT; kt++) {
        if (kt + 1 < KT) cp_wait<1>(); else cp_wait<0>();
        __syncthreads();
        if (kt + 2 < KT) load_stage((kt + 2) % STAGES, kt + 2);

        const uint32_t ab = sbase + (kt % STAGES) * STAGE_BYTES;
        const uint32_t bb = ab + A_BYTES;

        #pragma unroll
        for (int ks = 0; ks < 4; ks++) {
            const uint32_t kb = ks * 32;
            uint32_t af[4][4], bf[4][4];
            #pragma unroll
            for (int mi = 0; mi < 4; mi++)
                ldsm_x4(af[mi], ab + SWZ(arow[mi] + kb + acol));
            #pragma unroll
            for (int bi = 0; bi < 4; bi++)
                ldsm_x4(bf[bi], bb + SWZ(brow[bi] + kb + bcol));
            #pragma unroll
            for (int mi = 0; mi < 4; mi++)
                #pragma unroll
                for (int nj = 0; nj < 8; nj++)
                    mma16816(acc[mi][nj], af[mi], &bf[nj >> 1][(nj & 1) * 2]);
        }
    }

    const float inv = 1.0f / 127.0f;
    #pragma unroll
    for (int mi = 0; mi < 4; mi++) {
        int r = m0 + wm + mi * 16 + (lane >> 2);
        #pragma unroll
        for (int nj = 0; nj < 8; nj++) {
            int col = n0 + wn + nj * 8 + (lane & 3) * 2;
            float s0 = scale[col] * inv;
            float s1 = scale[col + 1] * inv;
            *(float2*)(outp + (size_t)r * N + col) =
                make_float2(acc[mi][nj][0] * s0, acc[mi][nj][1] * s1);
            *(float2*)(outp + (size_t)(r + 8) * N + col) =
                make_float2(acc[mi][nj][2] * s0, acc[mi][nj][3] * s1);
        }
    }
}

// ------------------------------ launcher -----------------------------------
extern "C" void kernel_launch(void* const* d_in, const int* in_sizes, int n_in,
                              void* d_out, int out_size) {
    const float* x  = (const float*)d_in[0];
    const void*  wg = d_in[1];
    const float* sg = (const float*)d_in[2];
    const void*  wu = d_in[3];
    const float* su = (const float*)d_in[4];
    const void*  wd = d_in[5];
    const float* sd = (const float*)d_in[6];

    const int H = in_sizes[6];            // 5120
    const int I = in_sizes[2];            // 12288
    const int M = in_sizes[0] / H;        // 4096

    __half *px16, *pwg, *pwu, *pwd, *ph;
    cudaGetSymbolAddress((void**)&px16, g_x16);
    cudaGetSymbolAddress((void**)&pwg,  g_wg16);
    cudaGetSymbolAddress((void**)&pwu,  g_wu16);
    cudaGetSymbolAddress((void**)&pwd,  g_wd16);
    cudaGetSymbolAddress((void**)&ph,   g_h);

    cudaFuncSetAttribute(gemm_gateup, cudaFuncAttributeMaxDynamicSharedMemorySize, SMEM_SZ);
    cudaFuncSetAttribute(gemm_down,   cudaFuncAttributeMaxDynamicSharedMemorySize, SMEM_SZ);

    detect_w_kernel<<<1, 32>>>((const int*)wg);

    {
        int n = M * H;
        cvt_f32_f16_kernel<<<(n / 4 + 255) / 256, 256>>>(x, px16, n);
        int nw = I * H;
        dim3 gw((nw / 8 + 255) / 256, 3);
        cvt_w_all_kernel<<<gw, 256>>>(wg, wu, wd, pwg, pwu, pwd, nw);
    }

    // Fused gate+up: h = silu(x@Wg^T*sg/127) * (x@Wu^T*su/127)   [M, I] fp16
    dim3 g1(M / 128, I / 128);   // (32, 96) — m fastest for L2 locality
    gemm_gateup<<<g1, 256, SMEM_SZ>>>(px16, pwg, pwu, sg, su, ph, I, H);

    // Down: out = (h @ Wd^T) * sd/127    [M, H] fp32
    dim3 g3(M / 128, H / 256);   // (32, 20)
    gemm_down<<<g3, 256, SMEM_SZ>>>(ph, pwd, sd, (float*)d_out, H, I);
}

// round 7
// speedup vs baseline: 1.5190x; 1.0061x over previous
#include <cuda_runtime.h>
#include <cuda_fp16.h>
#include <cstdint>
#include <math.h>

// ---------------------------------------------------------------------------
// QuantDeepseekMLP on sm_103a (legacy mma.sync; tcgen05 PTX rejected by the
// harness's compute_103 virtual arch).
// R7: gateup 4-stage pipeline (wait<=2 outstanding), down GEMM 128x128 tile
// at 2 CTAs/SM (finer wave granularity + cross-CTA latency hiding).
// ---------------------------------------------------------------------------

#define Mdim 4096
#define Hdim 5120
#define Idim 12288

__device__ __half g_x16[(size_t)Mdim * Hdim];
__device__ __half g_wg16[(size_t)Idim * Hdim];
__device__ __half g_wu16[(size_t)Idim * Hdim];
__device__ __half g_wd16[(size_t)Hdim * Idim];
__device__ __half g_h[(size_t)Mdim * Idim];
__device__ int g_wflag;   // 0=int8, 1=int32, 2=float32 weight storage

// ------------------------- dtype detection --------------------------------
__global__ void detect_w_kernel(const int* __restrict__ w) {
    if (threadIdx.x == 0 && blockIdx.x == 0) {
        int all_i32 = 1, all_f32 = 1;
        for (int i = 0; i < 256; i++) {
            int v = w[i];
            if (v < -127 || v > 127) all_i32 = 0;
            float f = __int_as_float(v);
            if (!(isfinite(f) && fabsf(f) <= 127.0f && f == rintf(f)))
                all_f32 = 0;
        }
        g_wflag = all_i32 ? 1 : (all_f32 ? 2 : 0);
    }
}

// ------------------------------ converters --------------------------------
__global__ void cvt_f32_f16_kernel(const float* __restrict__ in,
                                   __half* __restrict__ out, int n) {
    int i = (blockIdx.x * blockDim.x + threadIdx.x) * 4;
    if (i < n) {
        float4 v = *(const float4*)(in + i);
        *(__half2*)(out + i)     = __floats2half2_rn(v.x, v.y);
        *(__half2*)(out + i + 2) = __floats2half2_rn(v.z, v.w);
    }
}

__device__ __forceinline__ void cvt_w8(const void* in, __half* out, int i) {
    const int flag = g_wflag;
    float v[8];
    if (flag == 1) {
        const int4* p = (const int4*)((const int*)in + i);
        int4 a = p[0], b = p[1];
        v[0]=(float)a.x; v[1]=(float)a.y; v[2]=(float)a.z; v[3]=(float)a.w;
        v[4]=(float)b.x; v[5]=(float)b.y; v[6]=(float)b.z; v[7]=(float)b.w;
    } else if (flag == 2) {
        const float4* p = (const float4*)((const float*)in + i);
        float4 a = p[0], b = p[1];
        v[0]=a.x; v[1]=a.y; v[2]=a.z; v[3]=a.w;
        v[4]=b.x; v[5]=b.y; v[6]=b.z; v[7]=b.w;
    } else {
        uint2 raw = *(const uint2*)((const int8_t*)in + i);
        const int8_t* b = (const int8_t*)&raw;
        #pragma unroll
        for (int j = 0; j < 8; j++) v[j] = (float)b[j];
    }
    #pragma unroll
    for (int j = 0; j < 8; j += 2)
        *(__half2*)(out + i + j) = __floats2half2_rn(v[j], v[j + 1]);
}

__global__ void cvt_w_all_kernel(const void* w0, const void* w1, const void* w2,
                                 __half* o0, __half* o1, __half* o2, int n) {
    int i = (blockIdx.x * blockDim.x + threadIdx.x) * 8;
    if (i >= n) return;
    const void* src = (blockIdx.y == 0) ? w0 : (blockIdx.y == 1) ? w1 : w2;
    __half* dst = (blockIdx.y == 0) ? o0 : (blockIdx.y == 1) ? o1 : o2;
    cvt_w8(src, dst, i);
}

// --------------------------- PTX helpers -----------------------------------
__device__ __forceinline__ uint32_t smem_u32(const void* p) {
    return (uint32_t)__cvta_generic_to_shared(p);
}
__device__ __forceinline__ void cp_async16(uint32_t smem, const void* gmem) {
    asm volatile("cp.async.cg.shared.global [%0], [%1], 16;\n" :: "r"(smem), "l"(gmem));
}
__device__ __forceinline__ void cp_commit() {
    asm volatile("cp.async.commit_group;\n" ::: "memory");
}
template <int N>
__device__ __forceinline__ void cp_wait() {
    asm volatile("cp.async.wait_group %0;\n" :: "n"(N) : "memory");
}
__device__ __forceinline__ void ldsm_x4(uint32_t* r, uint32_t addr) {
    asm volatile("ldmatrix.sync.aligned.m8n8.x4.shared.b16 {%0,%1,%2,%3}, [%4];"
                 : "=r"(r[0]), "=r"(r[1]), "=r"(r[2]), "=r"(r[3]) : "r"(addr));
}
__device__ __forceinline__ void mma16816(float* d, const uint32_t* a,
                                         const uint32_t* b) {
    asm volatile(
        "mma.sync.aligned.m16n8k16.row.col.f32.f16.f16.f32 "
        "{%0,%1,%2,%3}, {%4,%5,%6,%7}, {%8,%9}, {%0,%1,%2,%3};\n"
        : "+f"(d[0]), "+f"(d[1]), "+f"(d[2]), "+f"(d[3])
        : "r"(a[0]), "r"(a[1]), "r"(a[2]), "r"(a[3]), "r"(b[0]), "r"(b[1]));
}

#define SWZ(o) ((o) ^ (((o) >> 3) & 0x70))

// ===================== fused gate+up GEMM (256 thr, 4 stages) ===============
#define GU_STAGES 4
#define GU_A_BYTES (128 * 128)
#define GU_STAGE_BYTES (GU_A_BYTES + 256 * 128)   // 48 KB
#define GU_SMEM (GU_STAGES * GU_STAGE_BYTES + 1024)

__global__ __launch_bounds__(256, 1)
void gemm_gateup(const __half* __restrict__ A, const __half* __restrict__ Bg_w,
                 const __half* __restrict__ Bu_w,
                 const float* __restrict__ sg, const float* __restrict__ su,
                 __half* __restrict__ outp, int N, int K) {
    extern __shared__ char smem_raw[];
    const uint32_t sbase = (smem_u32(smem_raw) + 1023) & ~1023u;

    const int tid  = threadIdx.x;
    const int lane = tid & 31;
    const int warp = tid >> 5;
    const int wm = (warp >> 2) * 64;
    const int wn = (warp & 3) * 64;           // virtual B-row offset
    const int m0 = blockIdx.x * 128;          // m fastest (L2 locality)
    const int n0 = blockIdx.y * 128;          // h column tile
    const int KT = K >> 6;

    const int g  = lane >> 3;
    const int li = lane & 7;

    const size_t pitch = (size_t)K * 2;
    const char* Ag = (const char*)A + (size_t)m0 * pitch;
    const char* Gg = (const char*)Bg_w + (size_t)n0 * pitch;
    const char* Ug = (const char*)Bu_w + (size_t)n0 * pitch;

    float acc[4][8][4];
    #pragma unroll
    for (int a = 0; a < 4; a++)
        #pragma unroll
        for (int b = 0; b < 8; b++)
            #pragma unroll
            for (int c = 0; c < 4; c++) acc[a][b][c] = 0.f;

    auto load_stage = [&](int slot, int kt) {
        const size_t k0b = (size_t)kt * 128;
        const uint32_t ab = sbase + slot * GU_STAGE_BYTES;
        const uint32_t bb = ab + GU_A_BYTES;
        #pragma unroll
        for (int i = 0; i < 12; i++) {
            int idx = i * 256 + tid;
            if (idx < 1024) {
                int r = idx >> 3, cb = (idx & 7) * 16;
                cp_async16(ab + SWZ(r * 128 + cb), Ag + (size_t)r * pitch + k0b + cb);
            } else {
                int j = idx - 1024;            // 0..2047
                int r = j >> 3, cb = (j & 7) * 16;
                int blk = r >> 5, within = r & 31;
                int w32 = (blk >> 1) * 32 + within;
                const char* src = (blk & 1) ? Ug : Gg;
                cp_async16(bb + SWZ(r * 128 + cb), src + (size_t)w32 * pitch + k0b + cb);
            }
        }
        cp_commit();
    };

    load_stage(0, 0);
    if (KT > 1) load_stage(1, 1);
    if (KT > 2) load_stage(2, 2);

    uint32_t arow[4], brow[4];
    #pragma unroll
    for (int mi = 0; mi < 4; mi++)
        arow[mi] = (uint32_t)(wm + mi * 16 + ((g & 1) ? 8 : 0) + li) * 128;
    #pragma unroll
    for (int bi = 0; bi < 4; bi++)
        brow[bi] = (uint32_t)(wn + bi * 16 + ((g >> 1) ? 8 : 0) + li) * 128;
    const uint32_t acol = (g >> 1) ? 16u : 0u;
    const uint32_t bcol = (g & 1) ? 16u : 0u;

    for (int kt = 0; kt < KT; kt++) {
        const int rem = KT - 1 - kt;
        if (rem >= 2)      cp_wait<2>();
        else if (rem == 1) cp_wait<1>();
        else               cp_wait<0>();
        __syncthreads();
        if (kt + 3 < KT) load_stage((kt + 3) % GU_STAGES, kt + 3);

        const uint32_t ab = sbase + (kt % GU_STAGES) * GU_STAGE_BYTES;
        const uint32_t bb = ab + GU_A_BYTES;

        #pragma unroll
        for (int ks = 0; ks < 4; ks++) {
            const uint32_t kb = ks * 32;
            uint32_t af[4][4], bf[4][4];
            #pragma unroll
            for (int mi = 0; mi < 4; mi++)
                ldsm_x4(af[mi], ab + SWZ(arow[mi] + kb + acol));
            #pragma unroll
            for (int bi = 0; bi < 4; bi++)
                ldsm_x4(bf[bi], bb + SWZ(brow[bi] + kb + bcol));
            #pragma unroll
            for (int mi = 0; mi < 4; mi++)
                #pragma unroll
                for (int nj = 0; nj < 8; nj++)
                    mma16816(acc[mi][nj], af[mi], &bf[nj >> 1][(nj & 1) * 2]);
        }
    }

    // epilogue: h = silu(gate*sg/127) * (up*su/127), fp16
    const float inv = 1.0f / 127.0f;
    const int cbase = n0 + (wn >> 1);
    #pragma unroll
    for (int mi = 0; mi < 4; mi++) {
        int r = m0 + wm + mi * 16 + (lane >> 2);
        #pragma unroll
        for (int nj = 0; nj < 4; nj++) {
            int col = cbase + nj * 8 + (lane & 3) * 2;
            float sg0 = sg[col] * inv, sg1 = sg[col + 1] * inv;
            float su0 = su[col] * inv, su1 = su[col + 1] * inv;
            float g00 = acc[mi][nj][0] * sg0, g01 = acc[mi][nj][1] * sg1;
            float g10 = acc[mi][nj][2] * sg0, g11 = acc[mi][nj][3] * sg1;
            float u00 = acc[mi][nj + 4][0] * su0, u01 = acc[mi][nj + 4][1] * su1;
            float u10 = acc[mi][nj + 4][2] * su0, u11 = acc[mi][nj + 4][3] * su1;
            float h00 = u00 * g00 / (1.0f + __expf(-g00));
            float h01 = u01 * g01 / (1.0f + __expf(-g01));
            float h10 = u10 * g10 / (1.0f + __expf(-g10));
            float h11 = u11 * g11 / (1.0f + __expf(-g11));
            *(__half2*)(outp + (size_t)r * N + col)       = __floats2half2_rn(h00, h01);
            *(__half2*)(outp + (size_t)(r + 8) * N + col) = __floats2half2_rn(h10, h11);
        }
    }
}

// ============ down GEMM: 128x128 tile, 128 threads, 2 CTAs/SM ===============
#define DN_STAGES 3
#define DN_A_BYTES (128 * 128)
#define DN_STAGE_BYTES (2 * DN_A_BYTES)            // 32 KB
#define DN_SMEM (DN_STAGES * DN_STAGE_BYTES + 1024)

__global__ __launch_bounds__(128, 2)
void gemm_down(const __half* __restrict__ A, const __half* __restrict__ Bw,
               const float* __restrict__ scale,
               float* __restrict__ outp, int N, int K) {
    extern __shared__ char smem_raw[];
    const uint32_t sbase = (smem_u32(smem_raw) + 1023) & ~1023u;

    const int tid  = threadIdx.x;
    const int lane = tid & 31;
    const int warp = tid >> 5;
    const int wm = (warp >> 1) * 64;          // 0 or 64
    const int wn = (warp & 1) * 64;           // 0 or 64
    const int m0 = blockIdx.x * 128;          // m fastest
    const int n0 = blockIdx.y * 128;
    const int KT = K >> 6;

    const int g  = lane >> 3;
    const int li = lane & 7;

    const size_t pitch = (size_t)K * 2;
    const char* Ag = (const char*)A + (size_t)m0 * pitch;
    const char* Bg = (const char*)Bw + (size_t)n0 * pitch;

    float acc[4][8][4];
    #pragma unroll
    for (int a = 0; a < 4; a++)
        #pragma unroll
        for (int b = 0; b < 8; b++)
            #pragma unroll
            for (int c = 0; c < 4; c++) acc[a][b][c] = 0.f;

    auto load_stage = [&](int slot, int kt) {
        const size_t k0b = (size_t)kt * 128;
        const uint32_t ab = sbase + slot * DN_STAGE_BYTES;
        const uint32_t bb = ab + DN_A_BYTES;
        #pragma unroll
        for (int i = 0; i < 16; i++) {
            int idx = i * 128 + tid;          // 0..2047
            if (idx < 1024) {
                int r = idx >> 3, cb = (idx & 7) * 16;
                cp_async16(ab + SWZ(r * 128 + cb), Ag + (size_t)r * pitch + k0b + cb);
            } else {
                int j = idx - 1024;
                int r = j >> 3, cb = (j & 7) * 16;
                cp_async16(bb + SWZ(r * 128 + cb), Bg + (size_t)r * pitch + k0b + cb);
            }
        }
        cp_commit();
    };

    load_stage(0, 0);
    if (KT > 1) load_stage(1, 1);

    uint32_t arow[4], brow[4];
    #pragma unroll
    for (int mi = 0; mi < 4; mi++)
        arow[mi] = (uint32_t)(wm + mi * 16 + ((g & 1) ? 8 : 0) + li) * 128;
    #pragma unroll
    for (int bi = 0; bi < 4; bi++)
        brow[bi] = (uint32_t)(wn + bi * 16 + ((g >> 1) ? 8 : 0) + li) * 128;
    const uint32_t acol = (g >> 1) ? 16u : 0u;
    const uint32_t bcol = (g & 1) ? 16u : 0u;

    for (int kt = 0; kt < KT; kt++) {
        const int rem = KT - 1 - kt;
        if (rem >= 1) cp_wait<1>(); else cp_wait<0>();
        __syncthreads();
        if (kt + 2 < KT) load_stage((kt + 2) % DN_STAGES, kt + 2);

        const uint32_t ab = sbase + (kt % DN_STAGES) * DN_STAGE_BYTES;
        const uint32_t bb = ab + DN_A_BYTES;

        #pragma unroll
        for (int ks = 0; ks < 4; ks++) {
            const uint32_t kb = ks * 32;
            uint32_t af[4][4], bf[4][4];
            #pragma unroll
            for (int mi = 0; mi < 4; mi++)
                ldsm_x4(af[mi], ab + SWZ(arow[mi] + kb + acol));
            #pragma unroll
            for (int bi = 0; bi < 4; bi++)
                ldsm_x4(bf[bi], bb + SWZ(brow[bi] + kb + bcol));
            #pragma unroll
            for (int mi = 0; mi < 4; mi++)
                #pragma unroll
                for (int nj = 0; nj < 8; nj++)
                    mma16816(acc[mi][nj], af[mi], &bf[nj >> 1][(nj & 1) * 2]);
        }
    }

    const float inv = 1.0f / 127.0f;
    #pragma unroll
    for (int mi = 0; mi < 4; mi++) {
        int r = m0 + wm + mi * 16 + (lane >> 2);
        #pragma unroll
        for (int nj = 0; nj < 8; nj++) {
            int col = n0 + wn + nj * 8 + (lane & 3) * 2;
            float s0 = scale[col] * inv;
            float s1 = scale[col + 1] * inv;
            *(float2*)(outp + (size_t)r * N + col) =
                make_float2(acc[mi][nj][0] * s0, acc[mi][nj][1] * s1);
            *(float2*)(outp + (size_t)(r + 8) * N + col) =
                make_float2(acc[mi][nj][2] * s0, acc[mi][nj][3] * s1);
        }
    }
}

// ------------------------------ launcher -----------------------------------
extern "C" void kernel_launch(void* const* d_in, const int* in_sizes, int n_in,
                              void* d_out, int out_size) {
    const float* x  = (const float*)d_in[0];
    const void*  wg = d_in[1];
    const float* sg = (const float*)d_in[2];
    const void*  wu = d_in[3];
    const float* su = (const float*)d_in[4];
    const void*  wd = d_in[5];
    const float* sd = (const float*)d_in[6];

    const int H = in_sizes[6];            // 5120
    const int I = in_sizes[2];            // 12288
    const int M = in_sizes[0] / H;        // 4096

    __half *px16, *pwg, *pwu, *pwd, *ph;
    cudaGetSymbolAddress((void**)&px16, g_x16);
    cudaGetSymbolAddress((void**)&pwg,  g_wg16);
    cudaGetSymbolAddress((void**)&pwu,  g_wu16);
    cudaGetSymbolAddress((void**)&pwd,  g_wd16);
    cudaGetSymbolAddress((void**)&ph,   g_h);

    cudaFuncSetAttribute(gemm_gateup, cudaFuncAttributeMaxDynamicSharedMemorySize, GU_SMEM);
    cudaFuncSetAttribute(gemm_down,   cudaFuncAttributeMaxDynamicSharedMemorySize, DN_SMEM);

    detect_w_kernel<<<1, 32>>>((const int*)wg);

    {
        int n = M * H;
        cvt_f32_f16_kernel<<<(n / 4 + 255) / 256, 256>>>(x, px16, n);
        int nw = I * H;
        dim3 gw((nw / 8 + 255) / 256, 3);
        cvt_w_all_kernel<<<gw, 256>>>(wg, wu, wd, pwg, pwu, pwd, nw);
    }

    // Fused gate+up: h = silu(x@Wg^T*sg/127) * (x@Wu^T*su/127)   [M, I] fp16
    dim3 g1(M / 128, I / 128);   // (32, 96)
    gemm_gateup<<<g1, 256, GU_SMEM>>>(px16, pwg, pwu, sg, su, ph, I, H);

    // Down: out = (h @ Wd^T) * sd/127    [M, H] fp32
    dim3 g3(M / 128, H / 128);   // (32, 40) = 1280 CTAs, 2/SM
    gemm_down<<<g3, 128, DN_SMEM>>>(ph, pwd, sd, (float*)d_out, H, I);
}

// round 9
// speedup vs baseline: 1.5655x; 1.0306x over previous
#include <cuda_runtime.h>
#include <cuda_fp16.h>
#include <cstdint>
#include <math.h>

// ---------------------------------------------------------------------------
// QuantDeepseekMLP on sm_103a (legacy mma.sync; tcgen05 PTX rejected by the
// harness's compute_103 virtual arch).
// R8: explicit register-fragment double buffering in both GEMM mainloops —
// LDSM for step ks+1 issues before the MMA block of step ks, hiding shared-
// memory latency under tensor work (R7 showed the stall is intra-warp).
// ---------------------------------------------------------------------------

#define Mdim 4096
#define Hdim 5120
#define Idim 12288

__device__ __half g_x16[(size_t)Mdim * Hdim];
__device__ __half g_wg16[(size_t)Idim * Hdim];
__device__ __half g_wu16[(size_t)Idim * Hdim];
__device__ __half g_wd16[(size_t)Hdim * Idim];
__device__ __half g_h[(size_t)Mdim * Idim];
__device__ int g_wflag;   // 0=int8, 1=int32, 2=float32 weight storage

// ------------------------- dtype detection --------------------------------
__global__ void detect_w_kernel(const int* __restrict__ w) {
    if (threadIdx.x == 0 && blockIdx.x == 0) {
        int all_i32 = 1, all_f32 = 1;
        for (int i = 0; i < 256; i++) {
            int v = w[i];
            if (v < -127 || v > 127) all_i32 = 0;
            float f = __int_as_float(v);
            if (!(isfinite(f) && fabsf(f) <= 127.0f && f == rintf(f)))
                all_f32 = 0;
        }
        g_wflag = all_i32 ? 1 : (all_f32 ? 2 : 0);
    }
}

// ------------------------------ converters --------------------------------
__global__ void cvt_f32_f16_kernel(const float* __restrict__ in,
                                   __half* __restrict__ out, int n) {
    int i = (blockIdx.x * blockDim.x + threadIdx.x) * 4;
    if (i < n) {
        float4 v = *(const float4*)(in + i);
        *(__half2*)(out + i)     = __floats2half2_rn(v.x, v.y);
        *(__half2*)(out + i + 2) = __floats2half2_rn(v.z, v.w);
    }
}

__device__ __forceinline__ void cvt_w8(const void* in, __half* out, int i) {
    const int flag = g_wflag;
    float v[8];
    if (flag == 1) {
        const int4* p = (const int4*)((const int*)in + i);
        int4 a = p[0], b = p[1];
        v[0]=(float)a.x; v[1]=(float)a.y; v[2]=(float)a.z; v[3]=(float)a.w;
        v[4]=(float)b.x; v[5]=(float)b.y; v[6]=(float)b.z; v[7]=(float)b.w;
    } else if (flag == 2) {
        const float4* p = (const float4*)((const float*)in + i);
        float4 a = p[0], b = p[1];
        v[0]=a.x; v[1]=a.y; v[2]=a.z; v[3]=a.w;
        v[4]=b.x; v[5]=b.y; v[6]=b.z; v[7]=b.w;
    } else {
        uint2 raw = *(const uint2*)((const int8_t*)in + i);
        const int8_t* b = (const int8_t*)&raw;
        #pragma unroll
        for (int j = 0; j < 8; j++) v[j] = (float)b[j];
    }
    #pragma unroll
    for (int j = 0; j < 8; j += 2)
        *(__half2*)(out + i + j) = __floats2half2_rn(v[j], v[j + 1]);
}

__global__ void cvt_w_all_kernel(const void* w0, const void* w1, const void* w2,
                                 __half* o0, __half* o1, __half* o2, int n) {
    int i = (blockIdx.x * blockDim.x + threadIdx.x) * 8;
    if (i >= n) return;
    const void* src = (blockIdx.y == 0) ? w0 : (blockIdx.y == 1) ? w1 : w2;
    __half* dst = (blockIdx.y == 0) ? o0 : (blockIdx.y == 1) ? o1 : o2;
    cvt_w8(src, dst, i);
}

// --------------------------- PTX helpers -----------------------------------
__device__ __forceinline__ uint32_t smem_u32(const void* p) {
    return (uint32_t)__cvta_generic_to_shared(p);
}
__device__ __forceinline__ void cp_async16(uint32_t smem, const void* gmem) {
    asm volatile("cp.async.cg.shared.global [%0], [%1], 16;\n" :: "r"(smem), "l"(gmem));
}
__device__ __forceinline__ void cp_commit() {
    asm volatile("cp.async.commit_group;\n" ::: "memory");
}
template <int N>
__device__ __forceinline__ void cp_wait() {
    asm volatile("cp.async.wait_group %0;\n" :: "n"(N) : "memory");
}
__device__ __forceinline__ void ldsm_x4(uint32_t* r, uint32_t addr) {
    asm volatile("ldmatrix.sync.aligned.m8n8.x4.shared.b16 {%0,%1,%2,%3}, [%4];"
                 : "=r"(r[0]), "=r"(r[1]), "=r"(r[2]), "=r"(r[3]) : "r"(addr));
}
__device__ __forceinline__ void mma16816(float* d, const uint32_t* a,
                                         const uint32_t* b) {
    asm volatile(
        "mma.sync.aligned.m16n8k16.row.col.f32.f16.f16.f32 "
        "{%0,%1,%2,%3}, {%4,%5,%6,%7}, {%8,%9}, {%0,%1,%2,%3};\n"
        : "+f"(d[0]), "+f"(d[1]), "+f"(d[2]), "+f"(d[3])
        : "r"(a[0]), "r"(a[1]), "r"(a[2]), "r"(a[3]), "r"(b[0]), "r"(b[1]));
}

#define SWZ(o) ((o) ^ (((o) >> 3) & 0x70))

// ===================== fused gate+up GEMM (256 thr, 4 stages) ===============
#define GU_STAGES 4
#define GU_A_BYTES (128 * 128)
#define GU_STAGE_BYTES (GU_A_BYTES + 256 * 128)   // 48 KB
#define GU_SMEM (GU_STAGES * GU_STAGE_BYTES + 1024)

__global__ __launch_bounds__(256, 1)
void gemm_gateup(const __half* __restrict__ A, const __half* __restrict__ Bg_w,
                 const __half* __restrict__ Bu_w,
                 const float* __restrict__ sg, const float* __restrict__ su,
                 __half* __restrict__ outp, int N, int K) {
    extern __shared__ char smem_raw[];
    const uint32_t sbase = (smem_u32(smem_raw) + 1023) & ~1023u;

    const int tid  = threadIdx.x;
    const int lane = tid & 31;
    const int warp = tid >> 5;
    const int wm = (warp >> 2) * 64;
    const int wn = (warp & 3) * 64;           // virtual B-row offset
    const int m0 = blockIdx.x * 128;          // m fastest (L2 locality)
    const int n0 = blockIdx.y * 128;          // h column tile
    const int KT = K >> 6;

    const int g  = lane >> 3;
    const int li = lane & 7;

    const size_t pitch = (size_t)K * 2;
    const char* Ag = (const char*)A + (size_t)m0 * pitch;
    const char* Gg = (const char*)Bg_w + (size_t)n0 * pitch;
    const char* Ug = (const char*)Bu_w + (size_t)n0 * pitch;

    float acc[4][8][4];
    #pragma unroll
    for (int a = 0; a < 4; a++)
        #pragma unroll
        for (int b = 0; b < 8; b++)
            #pragma unroll
            for (int c = 0; c < 4; c++) acc[a][b][c] = 0.f;

    auto load_stage = [&](int slot, int kt) {
        const size_t k0b = (size_t)kt * 128;
        const uint32_t ab = sbase + slot * GU_STAGE_BYTES;
        const uint32_t bb = ab + GU_A_BYTES;
        #pragma unroll
        for (int i = 0; i < 12; i++) {
            int idx = i * 256 + tid;
            if (idx < 1024) {
                int r = idx >> 3, cb = (idx & 7) * 16;
                cp_async16(ab + SWZ(r * 128 + cb), Ag + (size_t)r * pitch + k0b + cb);
            } else {
                int j = idx - 1024;            // 0..2047
                int r = j >> 3, cb = (j & 7) * 16;
                int blk = r >> 5, within = r & 31;
                int w32 = (blk >> 1) * 32 + within;
                const char* src = (blk & 1) ? Ug : Gg;
                cp_async16(bb + SWZ(r * 128 + cb), src + (size_t)w32 * pitch + k0b + cb);
            }
        }
        cp_commit();
    };

    load_stage(0, 0);
    if (KT > 1) load_stage(1, 1);
    if (KT > 2) load_stage(2, 2);

    uint32_t arow[4], brow[4];
    #pragma unroll
    for (int mi = 0; mi < 4; mi++)
        arow[mi] = (uint32_t)(wm + mi * 16 + ((g & 1) ? 8 : 0) + li) * 128;
    #pragma unroll
    for (int bi = 0; bi < 4; bi++)
        brow[bi] = (uint32_t)(wn + bi * 16 + ((g >> 1) ? 8 : 0) + li) * 128;
    const uint32_t acol = (g >> 1) ? 16u : 0u;
    const uint32_t bcol = (g & 1) ? 16u : 0u;

    // double-buffered register fragments
    uint32_t af[2][4][4], bf[2][4][4];

    for (int kt = 0; kt < KT; kt++) {
        const int rem = KT - 1 - kt;
        if (rem >= 2)      cp_wait<2>();
        else if (rem == 1) cp_wait<1>();
        else               cp_wait<0>();
        __syncthreads();
        if (kt + 3 < KT) load_stage((kt + 3) % GU_STAGES, kt + 3);

        const uint32_t ab = sbase + (kt % GU_STAGES) * GU_STAGE_BYTES;
        const uint32_t bb = ab + GU_A_BYTES;

        // prime ks=0 fragments
        #pragma unroll
        for (int mi = 0; mi < 4; mi++)
            ldsm_x4(af[0][mi], ab + SWZ(arow[mi] + acol));
        #pragma unroll
        for (int bi = 0; bi < 4; bi++)
            ldsm_x4(bf[0][bi], bb + SWZ(brow[bi] + bcol));

        #pragma unroll
        for (int ks = 0; ks < 4; ks++) {
            const int cur = ks & 1, nxt = cur ^ 1;
            if (ks < 3) {                      // prefetch ks+1 fragments
                const uint32_t kb = (ks + 1) * 32;
                #pragma unroll
                for (int mi = 0; mi < 4; mi++)
                    ldsm_x4(af[nxt][mi], ab + SWZ(arow[mi] + kb + acol));
                #pragma unroll
                for (int bi = 0; bi < 4; bi++)
                    ldsm_x4(bf[nxt][bi], bb + SWZ(brow[bi] + kb + bcol));
            }
            #pragma unroll
            for (int mi = 0; mi < 4; mi++)
                #pragma unroll
                for (int nj = 0; nj < 8; nj++)
                    mma16816(acc[mi][nj], af[cur][mi], &bf[cur][nj >> 1][(nj & 1) * 2]);
        }
    }

    // epilogue: h = silu(gate*sg/127) * (up*su/127), fp16
    const float inv = 1.0f / 127.0f;
    const int cbase = n0 + (wn >> 1);
    #pragma unroll
    for (int mi = 0; mi < 4; mi++) {
        int r = m0 + wm + mi * 16 + (lane >> 2);
        #pragma unroll
        for (int nj = 0; nj < 4; nj++) {
            int col = cbase + nj * 8 + (lane & 3) * 2;
            float sg0 = sg[col] * inv, sg1 = sg[col + 1] * inv;
            float su0 = su[col] * inv, su1 = su[col + 1] * inv;
            float g00 = acc[mi][nj][0] * sg0, g01 = acc[mi][nj][1] * sg1;
            float g10 = acc[mi][nj][2] * sg0, g11 = acc[mi][nj][3] * sg1;
            float u00 = acc[mi][nj + 4][0] * su0, u01 = acc[mi][nj + 4][1] * su1;
            float u10 = acc[mi][nj + 4][2] * su0, u11 = acc[mi][nj + 4][3] * su1;
            float h00 = u00 * g00 / (1.0f + __expf(-g00));
            float h01 = u01 * g01 / (1.0f + __expf(-g01));
            float h10 = u10 * g10 / (1.0f + __expf(-g10));
            float h11 = u11 * g11 / (1.0f + __expf(-g11));
            *(__half2*)(outp + (size_t)r * N + col)       = __floats2half2_rn(h00, h01);
            *(__half2*)(outp + (size_t)(r + 8) * N + col) = __floats2half2_rn(h10, h11);
        }
    }
}

// ============ down GEMM: 128x128 tile, 128 threads, 2 CTAs/SM ===============
#define DN_STAGES 3
#define DN_A_BYTES (128 * 128)
#define DN_STAGE_BYTES (2 * DN_A_BYTES)            // 32 KB
#define DN_SMEM (DN_STAGES * DN_STAGE_BYTES + 1024)

__global__ __launch_bounds__(128, 2)
void gemm_down(const __half* __restrict__ A, const __half* __restrict__ Bw,
               const float* __restrict__ scale,
               float* __restrict__ outp, int N, int K) {
    extern __shared__ char smem_raw[];
    const uint32_t sbase = (smem_u32(smem_raw) + 1023) & ~1023u;

    const int tid  = threadIdx.x;
    const int lane = tid & 31;
    const int warp = tid >> 5;
    const int wm = (warp >> 1) * 64;          // 0 or 64
    const int wn = (warp & 1) * 64;           // 0 or 64
    const int m0 = blockIdx.x * 128;          // m fastest
    const int n0 = blockIdx.y * 128;
    const int KT = K >> 6;

    const int g  = lane >> 3;
    const int li = lane & 7;

    const size_t pitch = (size_t)K * 2;
    const char* Ag = (const char*)A + (size_t)m0 * pitch;
    const char* Bg = (const char*)Bw + (size_t)n0 * pitch;

    float acc[4][8][4];
    #pragma unroll
    for (int a = 0; a < 4; a++)
        #pragma unroll
        for (int b = 0; b < 8; b++)
            #pragma unroll
            for (int c = 0; c < 4; c++) acc[a][b][c] = 0.f;

    auto load_stage = [&](int slot, int kt) {
        const size_t k0b = (size_t)kt * 128;
        const uint32_t ab = sbase + slot * DN_STAGE_BYTES;
        const uint32_t bb = ab + DN_A_BYTES;
        #pragma unroll
        for (int i = 0; i < 16; i++) {
            int idx = i * 128 + tid;          // 0..2047
            if (idx < 1024) {
                int r = idx >> 3, cb = (idx & 7) * 16;
                cp_async16(ab + SWZ(r * 128 + cb), Ag + (size_t)r * pitch + k0b + cb);
            } else {
                int j = idx - 1024;
                int r = j >> 3, cb = (j & 7) * 16;
                cp_async16(bb + SWZ(r * 128 + cb), Bg + (size_t)r * pitch + k0b + cb);
            }
        }
        cp_commit();
    };

    load_stage(0, 0);
    if (KT > 1) load_stage(1, 1);

    uint32_t arow[4], brow[4];
    #pragma unroll
    for (int mi = 0; mi < 4; mi++)
        arow[mi] = (uint32_t)(wm + mi * 16 + ((g & 1) ? 8 : 0) + li) * 128;
    #pragma unroll
    for (int bi = 0; bi < 4; bi++)
        brow[bi] = (uint32_t)(wn + bi * 16 + ((g >> 1) ? 8 : 0) + li) * 128;
    const uint32_t acol = (g >> 1) ? 16u : 0u;
    const uint32_t bcol = (g & 1) ? 16u : 0u;

    uint32_t af[2][4][4], bf[2][4][4];

    for (int kt = 0; kt < KT; kt++) {
        const int rem = KT - 1 - kt;
        if (rem >= 1) cp_wait<1>(); else cp_wait<0>();
        __syncthreads();
        if (kt + 2 < KT) load_stage((kt + 2) % DN_STAGES, kt + 2);

        const uint32_t ab = sbase + (kt % DN_STAGES) * DN_STAGE_BYTES;
        const uint32_t bb = ab + DN_A_BYTES;

        #pragma unroll
        for (int mi = 0; mi < 4; mi++)
            ldsm_x4(af[0][mi], ab + SWZ(arow[mi] + acol));
        #pragma unroll
        for (int bi = 0; bi < 4; bi++)
            ldsm_x4(bf[0][bi], bb + SWZ(brow[bi] + bcol));

        #pragma unroll
        for (int ks = 0; ks < 4; ks++) {
            const int cur = ks & 1, nxt = cur ^ 1;
            if (ks < 3) {
                const uint32_t kb = (ks + 1) * 32;
                #pragma unroll
                for (int mi = 0; mi < 4; mi++)
                    ldsm_x4(af[nxt][mi], ab + SWZ(arow[mi] + kb + acol));
                #pragma unroll
                for (int bi = 0; bi < 4; bi++)
                    ldsm_x4(bf[nxt][bi], bb + SWZ(brow[bi] + kb + bcol));
            }
            #pragma unroll
            for (int mi = 0; mi < 4; mi++)
                #pragma unroll
                for (int nj = 0; nj < 8; nj++)
                    mma16816(acc[mi][nj], af[cur][mi], &bf[cur][nj >> 1][(nj & 1) * 2]);
        }
    }

    const float inv = 1.0f / 127.0f;
    #pragma unroll
    for (int mi = 0; mi < 4; mi++) {
        int r = m0 + wm + mi * 16 + (lane >> 2);
        #pragma unroll
        for (int nj = 0; nj < 8; nj++) {
            int col = n0 + wn + nj * 8 + (lane & 3) * 2;
            float s0 = scale[col] * inv;
            float s1 = scale[col + 1] * inv;
            *(float2*)(outp + (size_t)r * N + col) =
                make_float2(acc[mi][nj][0] * s0, acc[mi][nj][1] * s1);
            *(float2*)(outp + (size_t)(r + 8) * N + col) =
                make_float2(acc[mi][nj][2] * s0, acc[mi][nj][3] * s1);
        }
    }
}

// ------------------------------ launcher -----------------------------------
extern "C" void kernel_launch(void* const* d_in, const int* in_sizes, int n_in,
                              void* d_out, int out_size) {
    const float* x  = (const float*)d_in[0];
    const void*  wg = d_in[1];
    const float* sg = (const float*)d_in[2];
    const void*  wu = d_in[3];
    const float* su = (const float*)d_in[4];
    const void*  wd = d_in[5];
    const float* sd = (const float*)d_in[6];

    const int H = in_sizes[6];            // 5120
    const int I = in_sizes[2];            // 12288
    const int M = in_sizes[0] / H;        // 4096

    __half *px16, *pwg, *pwu, *pwd, *ph;
    cudaGetSymbolAddress((void**)&px16, g_x16);
    cudaGetSymbolAddress((void**)&pwg,  g_wg16);
    cudaGetSymbolAddress((void**)&pwu,  g_wu16);
    cudaGetSymbolAddress((void**)&pwd,  g_wd16);
    cudaGetSymbolAddress((void**)&ph,   g_h);

    cudaFuncSetAttribute(gemm_gateup, cudaFuncAttributeMaxDynamicSharedMemorySize, GU_SMEM);
    cudaFuncSetAttribute(gemm_down,   cudaFuncAttributeMaxDynamicSharedMemorySize, DN_SMEM);

    detect_w_kernel<<<1, 32>>>((const int*)wg);

    {
        int n = M * H;
        cvt_f32_f16_kernel<<<(n / 4 + 255) / 256, 256>>>(x, px16, n);
        int nw = I * H;
        dim3 gw((nw / 8 + 255) / 256, 3);
        cvt_w_all_kernel<<<gw, 256>>>(wg, wu, wd, pwg, pwu, pwd, nw);
    }

    // Fused gate+up: h = silu(x@Wg^T*sg/127) * (x@Wu^T*su/127)   [M, I] fp16
    dim3 g1(M / 128, I / 128);   // (32, 96)
    gemm_gateup<<<g1, 256, GU_SMEM>>>(px16, pwg, pwu, sg, su, ph, I, H);

    // Down: out = (h @ Wd^T) * sd/127    [M, H] fp32
    dim3 g3(M / 128, H / 128);   // (32, 40) = 1280 CTAs, 2/SM
    gemm_down<<<g3, 128, DN_SMEM>>>(ph, pwd, sd, (float*)d_out, H, I);
}

// round 10
// speedup vs baseline: 1.6427x; 1.0493x over previous
#include <cuda_runtime.h>
#include <cuda_fp16.h>
#include <cstdint>
#include <math.h>

// ---------------------------------------------------------------------------
// QuantDeepseekMLP on sm_103a (legacy mma.sync; tcgen05 PTX rejected by the
// harness's compute_103 virtual arch).
// R10: gateup re-tiled to 128x64 h-tile, 128 threads, 2 CTAs/SM — co-resident
// CTAs cover each other's barrier/prime bubbles (R8/R9 showed intra-warp
// scheduling can't move tensor% at 1 CTA/SM).
// ---------------------------------------------------------------------------

#define Mdim 4096
#define Hdim 5120
#define Idim 12288

__device__ __half g_x16[(size_t)Mdim * Hdim];
__device__ __half g_wg16[(size_t)Idim * Hdim];
__device__ __half g_wu16[(size_t)Idim * Hdim];
__device__ __half g_wd16[(size_t)Hdim * Idim];
__device__ __half g_h[(size_t)Mdim * Idim];
__device__ int g_wflag;   // 0=int8, 1=int32, 2=float32 weight storage

// ------------------------- dtype detection --------------------------------
__global__ void detect_w_kernel(const int* __restrict__ w) {
    if (threadIdx.x == 0 && blockIdx.x == 0) {
        int all_i32 = 1, all_f32 = 1;
        for (int i = 0; i < 256; i++) {
            int v = w[i];
            if (v < -127 || v > 127) all_i32 = 0;
            float f = __int_as_float(v);
            if (!(isfinite(f) && fabsf(f) <= 127.0f && f == rintf(f)))
                all_f32 = 0;
        }
        g_wflag = all_i32 ? 1 : (all_f32 ? 2 : 0);
    }
}

// ------------------------------ converters --------------------------------
__global__ void cvt_f32_f16_kernel(const float* __restrict__ in,
                                   __half* __restrict__ out, int n) {
    int i = (blockIdx.x * blockDim.x + threadIdx.x) * 4;
    if (i < n) {
        float4 v = *(const float4*)(in + i);
        *(__half2*)(out + i)     = __floats2half2_rn(v.x, v.y);
        *(__half2*)(out + i + 2) = __floats2half2_rn(v.z, v.w);
    }
}

__device__ __forceinline__ void cvt_w8(const void* in, __half* out, int i) {
    const int flag = g_wflag;
    float v[8];
    if (flag == 1) {
        const int4* p = (const int4*)((const int*)in + i);
        int4 a = p[0], b = p[1];
        v[0]=(float)a.x; v[1]=(float)a.y; v[2]=(float)a.z; v[3]=(float)a.w;
        v[4]=(float)b.x; v[5]=(float)b.y; v[6]=(float)b.z; v[7]=(float)b.w;
    } else if (flag == 2) {
        const float4* p = (const float4*)((const float*)in + i);
        float4 a = p[0], b = p[1];
        v[0]=a.x; v[1]=a.y; v[2]=a.z; v[3]=a.w;
        v[4]=b.x; v[5]=b.y; v[6]=b.z; v[7]=b.w;
    } else {
        uint2 raw = *(const uint2*)((const int8_t*)in + i);
        const int8_t* b = (const int8_t*)&raw;
        #pragma unroll
        for (int j = 0; j < 8; j++) v[j] = (float)b[j];
    }
    #pragma unroll
    for (int j = 0; j < 8; j += 2)
        *(__half2*)(out + i + j) = __floats2half2_rn(v[j], v[j + 1]);
}

__global__ void cvt_w_all_kernel(const void* w0, const void* w1, const void* w2,
                                 __half* o0, __half* o1, __half* o2, int n) {
    int i = (blockIdx.x * blockDim.x + threadIdx.x) * 8;
    if (i >= n) return;
    const void* src = (blockIdx.y == 0) ? w0 : (blockIdx.y == 1) ? w1 : w2;
    __half* dst = (blockIdx.y == 0) ? o0 : (blockIdx.y == 1) ? o1 : o2;
    cvt_w8(src, dst, i);
}

// --------------------------- PTX helpers -----------------------------------
__device__ __forceinline__ uint32_t smem_u32(const void* p) {
    return (uint32_t)__cvta_generic_to_shared(p);
}
__device__ __forceinline__ void cp_async16(uint32_t smem, const void* gmem) {
    asm volatile("cp.async.cg.shared.global [%0], [%1], 16;\n" :: "r"(smem), "l"(gmem));
}
__device__ __forceinline__ void cp_commit() {
    asm volatile("cp.async.commit_group;\n" ::: "memory");
}
template <int N>
__device__ __forceinline__ void cp_wait() {
    asm volatile("cp.async.wait_group %0;\n" :: "n"(N) : "memory");
}
__device__ __forceinline__ void ldsm_x4(uint32_t* r, uint32_t addr) {
    asm volatile("ldmatrix.sync.aligned.m8n8.x4.shared.b16 {%0,%1,%2,%3}, [%4];"
                 : "=r"(r[0]), "=r"(r[1]), "=r"(r[2]), "=r"(r[3]) : "r"(addr));
}
__device__ __forceinline__ void mma16816(float* d, const uint32_t* a,
                                         const uint32_t* b) {
    asm volatile(
        "mma.sync.aligned.m16n8k16.row.col.f32.f16.f16.f32 "
        "{%0,%1,%2,%3}, {%4,%5,%6,%7}, {%8,%9}, {%0,%1,%2,%3};\n"
        : "+f"(d[0]), "+f"(d[1]), "+f"(d[2]), "+f"(d[3])
        : "r"(a[0]), "r"(a[1]), "r"(a[2]), "r"(a[3]), "r"(b[0]), "r"(b[1]));
}

#define SWZ(o) ((o) ^ (((o) >> 3) & 0x70))

// =========== fused gate+up GEMM: 128x64 h-tile, 128 thr, 2 CTAs/SM =========
// B smem 128 rows interleaves: [g(c0..31) | u(c0..31) | g(c32..63) | u(c32..63)]
// Warp grid 2x2: wm = (warp>>1)*64, wn = (warp&1)*64 (virtual B rows).
// acc[mi][nj] nj<4 = gate, nj>=4 = up, for h cols [n0+(wn>>1), +32).
#define GU_STAGES 3
#define GU_A_BYTES (128 * 128)
#define GU_STAGE_BYTES (GU_A_BYTES + 128 * 128)    // 32 KB
#define GU_SMEM (GU_STAGES * GU_STAGE_BYTES + 1024)

__global__ __launch_bounds__(128, 2)
void gemm_gateup(const __half* __restrict__ A, const __half* __restrict__ Bg_w,
                 const __half* __restrict__ Bu_w,
                 const float* __restrict__ sg, const float* __restrict__ su,
                 __half* __restrict__ outp, int N, int K) {
    extern __shared__ char smem_raw[];
    const uint32_t sbase = (smem_u32(smem_raw) + 1023) & ~1023u;

    const int tid  = threadIdx.x;
    const int lane = tid & 31;
    const int warp = tid >> 5;
    const int wm = (warp >> 1) * 64;
    const int wn = (warp & 1) * 64;           // virtual B-row offset
    const int m0 = blockIdx.x * 128;          // m fastest (L2 locality)
    const int n0 = blockIdx.y * 64;           // h column tile (64 wide)
    const int KT = K >> 6;

    const int g  = lane >> 3;
    const int li = lane & 7;

    const size_t pitch = (size_t)K * 2;
    const char* Ag = (const char*)A + (size_t)m0 * pitch;
    const char* Gg = (const char*)Bg_w + (size_t)n0 * pitch;
    const char* Ug = (const char*)Bu_w + (size_t)n0 * pitch;

    float acc[4][8][4];
    #pragma unroll
    for (int a = 0; a < 4; a++)
        #pragma unroll
        for (int b = 0; b < 8; b++)
            #pragma unroll
            for (int c = 0; c < 4; c++) acc[a][b][c] = 0.f;

    auto load_stage = [&](int slot, int kt) {
        const size_t k0b = (size_t)kt * 128;
        const uint32_t ab = sbase + slot * GU_STAGE_BYTES;
        const uint32_t bb = ab + GU_A_BYTES;
        #pragma unroll
        for (int i = 0; i < 16; i++) {
            int idx = i * 128 + tid;           // 0..2047
            if (idx < 1024) {                  // A: 128 rows
                int r = idx >> 3, cb = (idx & 7) * 16;
                cp_async16(ab + SWZ(r * 128 + cb), Ag + (size_t)r * pitch + k0b + cb);
            } else {                           // B: 128 virtual rows
                int j = idx - 1024;            // 0..1023
                int r = j >> 3, cb = (j & 7) * 16;
                int blk = r >> 5, within = r & 31;
                int w32 = (blk >> 1) * 32 + within;   // row in 64-col tile
                const char* src = (blk & 1) ? Ug : Gg;
                cp_async16(bb + SWZ(r * 128 + cb), src + (size_t)w32 * pitch + k0b + cb);
            }
        }
        cp_commit();
    };

    load_stage(0, 0);
    if (KT > 1) load_stage(1, 1);

    uint32_t arow[4], brow[4];
    #pragma unroll
    for (int mi = 0; mi < 4; mi++)
        arow[mi] = (uint32_t)(wm + mi * 16 + ((g & 1) ? 8 : 0) + li) * 128;
    #pragma unroll
    for (int bi = 0; bi < 4; bi++)
        brow[bi] = (uint32_t)(wn + bi * 16 + ((g >> 1) ? 8 : 0) + li) * 128;
    const uint32_t acol = (g >> 1) ? 16u : 0u;
    const uint32_t bcol = (g & 1) ? 16u : 0u;

    uint32_t af[2][4][4], bf[2][4][4];

    for (int kt = 0; kt < KT; kt++) {
        const int rem = KT - 1 - kt;
        if (rem >= 1) cp_wait<1>(); else cp_wait<0>();
        __syncthreads();
        if (kt + 2 < KT) load_stage((kt + 2) % GU_STAGES, kt + 2);

        const uint32_t ab = sbase + (kt % GU_STAGES) * GU_STAGE_BYTES;
        const uint32_t bb = ab + GU_A_BYTES;

        #pragma unroll
        for (int mi = 0; mi < 4; mi++)
            ldsm_x4(af[0][mi], ab + SWZ(arow[mi] + acol));
        #pragma unroll
        for (int bi = 0; bi < 4; bi++)
            ldsm_x4(bf[0][bi], bb + SWZ(brow[bi] + bcol));

        #pragma unroll
        for (int ks = 0; ks < 4; ks++) {
            const int cur = ks & 1, nxt = cur ^ 1;
            if (ks < 3) {
                const uint32_t kb = (ks + 1) * 32;
                #pragma unroll
                for (int mi = 0; mi < 4; mi++)
                    ldsm_x4(af[nxt][mi], ab + SWZ(arow[mi] + kb + acol));
                #pragma unroll
                for (int bi = 0; bi < 4; bi++)
                    ldsm_x4(bf[nxt][bi], bb + SWZ(brow[bi] + kb + bcol));
            }
            #pragma unroll
            for (int mi = 0; mi < 4; mi++)
                #pragma unroll
                for (int nj = 0; nj < 8; nj++)
                    mma16816(acc[mi][nj], af[cur][mi], &bf[cur][nj >> 1][(nj & 1) * 2]);
        }
    }

    // epilogue: h = silu(gate*sg/127) * (up*su/127), fp16
    const float inv = 1.0f / 127.0f;
    const int cbase = n0 + (wn >> 1);
    #pragma unroll
    for (int mi = 0; mi < 4; mi++) {
        int r = m0 + wm + mi * 16 + (lane >> 2);
        #pragma unroll
        for (int nj = 0; nj < 4; nj++) {
            int col = cbase + nj * 8 + (lane & 3) * 2;
            float sg0 = sg[col] * inv, sg1 = sg[col + 1] * inv;
            float su0 = su[col] * inv, su1 = su[col + 1] * inv;
            float g00 = acc[mi][nj][0] * sg0, g01 = acc[mi][nj][1] * sg1;
            float g10 = acc[mi][nj][2] * sg0, g11 = acc[mi][nj][3] * sg1;
            float u00 = acc[mi][nj + 4][0] * su0, u01 = acc[mi][nj + 4][1] * su1;
            float u10 = acc[mi][nj + 4][2] * su0, u11 = acc[mi][nj + 4][3] * su1;
            float h00 = u00 * g00 / (1.0f + __expf(-g00));
            float h01 = u01 * g01 / (1.0f + __expf(-g01));
            float h10 = u10 * g10 / (1.0f + __expf(-g10));
            float h11 = u11 * g11 / (1.0f + __expf(-g11));
            *(__half2*)(outp + (size_t)r * N + col)       = __floats2half2_rn(h00, h01);
            *(__half2*)(outp + (size_t)(r + 8) * N + col) = __floats2half2_rn(h10, h11);
        }
    }
}

// ============ down GEMM: 128x128 tile, 128 threads, 2 CTAs/SM ===============
#define DN_STAGES 3
#define DN_A_BYTES (128 * 128)
#define DN_STAGE_BYTES (2 * DN_A_BYTES)            // 32 KB
#define DN_SMEM (DN_STAGES * DN_STAGE_BYTES + 1024)

__global__ __launch_bounds__(128, 2)
void gemm_down(const __half* __restrict__ A, const __half* __restrict__ Bw,
               const float* __restrict__ scale,
               float* __restrict__ outp, int N, int K) {
    extern __shared__ char smem_raw[];
    const uint32_t sbase = (smem_u32(smem_raw) + 1023) & ~1023u;

    const int tid  = threadIdx.x;
    const int lane = tid & 31;
    const int warp = tid >> 5;
    const int wm = (warp >> 1) * 64;          // 0 or 64
    const int wn = (warp & 1) * 64;           // 0 or 64
    const int m0 = blockIdx.x * 128;          // m fastest
    const int n0 = blockIdx.y * 128;
    const int KT = K >> 6;

    const int g  = lane >> 3;
    const int li = lane & 7;

    const size_t pitch = (size_t)K * 2;
    const char* Ag = (const char*)A + (size_t)m0 * pitch;
    const char* Bg = (const char*)Bw + (size_t)n0 * pitch;

    float acc[4][8][4];
    #pragma unroll
    for (int a = 0; a < 4; a++)
        #pragma unroll
        for (int b = 0; b < 8; b++)
            #pragma unroll
            for (int c = 0; c < 4; c++) acc[a][b][c] = 0.f;

    auto load_stage = [&](int slot, int kt) {
        const size_t k0b = (size_t)kt * 128;
        const uint32_t ab = sbase + slot * DN_STAGE_BYTES;
        const uint32_t bb = ab + DN_A_BYTES;
        #pragma unroll
        for (int i = 0; i < 16; i++) {
            int idx = i * 128 + tid;          // 0..2047
            if (idx < 1024) {
                int r = idx >> 3, cb = (idx & 7) * 16;
                cp_async16(ab + SWZ(r * 128 + cb), Ag + (size_t)r * pitch + k0b + cb);
            } else {
                int j = idx - 1024;
                int r = j >> 3, cb = (j & 7) * 16;
                cp_async16(bb + SWZ(r * 128 + cb), Bg + (size_t)r * pitch + k0b + cb);
            }
        }
        cp_commit();
    };

    load_stage(0, 0);
    if (KT > 1) load_stage(1, 1);

    uint32_t arow[4], brow[4];
    #pragma unroll
    for (int mi = 0; mi < 4; mi++)
        arow[mi] = (uint32_t)(wm + mi * 16 + ((g & 1) ? 8 : 0) + li) * 128;
    #pragma unroll
    for (int bi = 0; bi < 4; bi++)
        brow[bi] = (uint32_t)(wn + bi * 16 + ((g >> 1) ? 8 : 0) + li) * 128;
    const uint32_t acol = (g >> 1) ? 16u : 0u;
    const uint32_t bcol = (g & 1) ? 16u : 0u;

    uint32_t af[2][4][4], bf[2][4][4];

    for (int kt = 0; kt < KT; kt++) {
        const int rem = KT - 1 - kt;
        if (rem >= 1) cp_wait<1>(); else cp_wait<0>();
        __syncthreads();
        if (kt + 2 < KT) load_stage((kt + 2) % DN_STAGES, kt + 2);

        const uint32_t ab = sbase + (kt % DN_STAGES) * DN_STAGE_BYTES;
        const uint32_t bb = ab + DN_A_BYTES;

        #pragma unroll
        for (int mi = 0; mi < 4; mi++)
            ldsm_x4(af[0][mi], ab + SWZ(arow[mi] + acol));
        #pragma unroll
        for (int bi = 0; bi < 4; bi++)
            ldsm_x4(bf[0][bi], bb + SWZ(brow[bi] + bcol));

        #pragma unroll
        for (int ks = 0; ks < 4; ks++) {
            const int cur = ks & 1, nxt = cur ^ 1;
            if (ks < 3) {
                const uint32_t kb = (ks + 1) * 32;
                #pragma unroll
                for (int mi = 0; mi < 4; mi++)
                    ldsm_x4(af[nxt][mi], ab + SWZ(arow[mi] + kb + acol));
                #pragma unroll
                for (int bi = 0; bi < 4; bi++)
                    ldsm_x4(bf[nxt][bi], bb + SWZ(brow[bi] + kb + bcol));
            }
            #pragma unroll
            for (int mi = 0; mi < 4; mi++)
                #pragma unroll
                for (int nj = 0; nj < 8; nj++)
                    mma16816(acc[mi][nj], af[cur][mi], &bf[cur][nj >> 1][(nj & 1) * 2]);
        }
    }

    const float inv = 1.0f / 127.0f;
    #pragma unroll
    for (int mi = 0; mi < 4; mi++) {
        int r = m0 + wm + mi * 16 + (lane >> 2);
        #pragma unroll
        for (int nj = 0; nj < 8; nj++) {
            int col = n0 + wn + nj * 8 + (lane & 3) * 2;
            float s0 = scale[col] * inv;
            float s1 = scale[col + 1] * inv;
            *(float2*)(outp + (size_t)r * N + col) =
                make_float2(acc[mi][nj][0] * s0, acc[mi][nj][1] * s1);
            *(float2*)(outp + (size_t)(r + 8) * N + col) =
                make_float2(acc[mi][nj][2] * s0, acc[mi][nj][3] * s1);
        }
    }
}

// ------------------------------ launcher -----------------------------------
extern "C" void kernel_launch(void* const* d_in, const int* in_sizes, int n_in,
                              void* d_out, int out_size) {
    const float* x  = (const float*)d_in[0];
    const void*  wg = d_in[1];
    const float* sg = (const float*)d_in[2];
    const void*  wu = d_in[3];
    const float* su = (const float*)d_in[4];
    const void*  wd = d_in[5];
    const float* sd = (const float*)d_in[6];

    const int H = in_sizes[6];            // 5120
    const int I = in_sizes[2];            // 12288
    const int M = in_sizes[0] / H;        // 4096

    __half *px16, *pwg, *pwu, *pwd, *ph;
    cudaGetSymbolAddress((void**)&px16, g_x16);
    cudaGetSymbolAddress((void**)&pwg,  g_wg16);
    cudaGetSymbolAddress((void**)&pwu,  g_wu16);
    cudaGetSymbolAddress((void**)&pwd,  g_wd16);
    cudaGetSymbolAddress((void**)&ph,   g_h);

    cudaFuncSetAttribute(gemm_gateup, cudaFuncAttributeMaxDynamicSharedMemorySize, GU_SMEM);
    cudaFuncSetAttribute(gemm_down,   cudaFuncAttributeMaxDynamicSharedMemorySize, DN_SMEM);

    detect_w_kernel<<<1, 32>>>((const int*)wg);

    {
        int n = M * H;
        cvt_f32_f16_kernel<<<(n / 4 + 255) / 256, 256>>>(x, px16, n);
        int nw = I * H;
        dim3 gw((nw / 8 + 255) / 256, 3);
        cvt_w_all_kernel<<<gw, 256>>>(wg, wu, wd, pwg, pwu, pwd, nw);
    }

    // Fused gate+up: h = silu(x@Wg^T*sg/127) * (x@Wu^T*su/127)   [M, I] fp16
    dim3 g1(M / 128, I / 64);    // (32, 192) — 2 CTAs/SM
    gemm_gateup<<<g1, 128, GU_SMEM>>>(px16, pwg, pwu, sg, su, ph, I, H);

    // Down: out = (h @ Wd^T) * sd/127    [M, H] fp32
    dim3 g3(M / 128, H / 128);   // (32, 40) — 2 CTAs/SM
    gemm_down<<<g3, 128, DN_SMEM>>>(ph, pwd, sd, (float*)d_out, H, I);
}